// round 9
// baseline (speedup 1.0000x reference)
#include <cuda_runtime.h>
#include <cstdint>

static constexpr int MAX_E = 1600000;             // < 2^21 (orig id fits 21 bits)
static constexpr int NROWS = 65536;               // row ids < 2^16
static constexpr int CAP   = 128;                 // slots per row bucket
static constexpr int ROWS_PER_BLK = 16;
static constexpr int NBLK_D = NROWS / ROWS_PER_BLK;  // 4096
static constexpr int CHUNK = 128;                 // arrwp rows per pipeline stage
static constexpr int FUSED_GRID = 888;            // 148 SMs x 6 blocks

// Scratch (allocation-free: __device__ globals)
__device__ unsigned long long g_bucket[(size_t)NROWS * CAP];  // (col<<32)|orig
__device__ int g_cnt[NROWS];
__device__ uint32_t g_segflag[MAX_E];             // per ORIGINAL edge: (seg<<1)|leader
__device__ unsigned long long g_desc[NBLK_D];     // lookback: (value<<2)|state
__device__ int g_blkctr;
__device__ int g_nu;

// ---------------------------------------------------------------------------
__device__ __forceinline__ uint32_t smem_u32(const void* p) {
    uint32_t a;
    asm("{ .reg .u64 t; cvta.to.shared.u64 t, %1; cvt.u32.u64 %0, t; }"
        : "=r"(a) : "l"(p));
    return a;
}
__device__ __forceinline__ void fma2(unsigned long long& acc,
                                     unsigned long long a, unsigned long long b) {
    asm("fma.rn.f32x2 %0, %1, %2, %0;" : "+l"(acc) : "l"(a), "l"(b));
}
__device__ __forceinline__ void mbar_init(uint32_t mbar, uint32_t cnt) {
    asm volatile("mbarrier.init.shared.b64 [%0], %1;" :: "r"(mbar), "r"(cnt) : "memory");
}
__device__ __forceinline__ void mbar_expect_tx(uint32_t mbar, uint32_t bytes) {
    asm volatile("mbarrier.arrive.expect_tx.shared.b64 _, [%0], %1;"
                 :: "r"(mbar), "r"(bytes) : "memory");
}
__device__ __forceinline__ void mbar_wait(uint32_t mbar, uint32_t parity) {
    uint32_t done;
    asm volatile(
        "{ .reg .pred p; mbarrier.try_wait.parity.acquire.cta.shared::cta.b64 p, [%1], %2;"
        " selp.b32 %0, 1, 0, p; }"
        : "=r"(done) : "r"(mbar), "r"(parity) : "memory");
    if (!done) {
        asm volatile(
            "{ .reg .pred P1; WL%=:"
            " mbarrier.try_wait.parity.acquire.cta.shared::cta.b64 P1, [%0], %1, 0x989680;"
            " @P1 bra.uni WD%=; bra.uni WL%=; WD%=: }"
            :: "r"(mbar), "r"(parity) : "memory");
    }
}
__device__ __forceinline__ void bulk_copy(uint32_t dst, const void* src,
                                          uint32_t bytes, uint32_t mbar) {
    asm volatile(
        "cp.async.bulk.shared::cta.global.mbarrier::complete_tx::bytes [%0], [%1], %2, [%3];"
        :: "r"(dst), "l"(src), "r"(bytes), "r"(mbar) : "memory");
}

// ---------------------------------------------------------------------------
// 0. per-launch reset
__global__ void k_init() {
    int i = blockIdx.x * blockDim.x + threadIdx.x;
    if (i < NROWS) g_cnt[i] = 0;
    if (i < NBLK_D) g_desc[i] = 0ull;
    if (i == 0) g_blkctr = 0;
}

// 1. bucket scatter: g_bucket[row*CAP + slot] = (col<<32)|orig
__global__ void k_bucket(const int* __restrict__ ei, const int* __restrict__ ai,
                         int Ee, int Ea) {
    int E = Ee + Ea;
    int i = blockIdx.x * blockDim.x + threadIdx.x;
    if (i >= E) return;
    int row, col;
    if (i < Ee) { row = ei[i];          col = ei[Ee + i]; }
    else        { int j = i - Ee; row = ai[j]; col = ai[Ea + j]; }
    int slot = atomicAdd(&g_cnt[row], 1);
    if (slot < CAP)
        g_bucket[(size_t)row * CAP + slot] =
            ((unsigned long long)(uint32_t)col << 32) | (unsigned long long)i;
}

// --- per-row machinery: u32 bitonic (size-adapted), flags, ranks ------------
template <int R>
__device__ __forceinline__ int row_phase1(const unsigned long long* __restrict__ eb,
                                          int n, int lane,
                                          uint32_t v[4], uint32_t og[4],
                                          int rk[4], int fl[4]) {
    const unsigned FULL = 0xFFFFFFFFu;
    #pragma unroll
    for (int k = 0; k < R; k++) {
        int p = k * 32 + lane;
        if (p < n) {
            unsigned long long e = eb[p];
            og[k] = (uint32_t)e;
            v[k]  = ((uint32_t)(e >> 32) << 8) | (uint32_t)p;  // (col<<8)|slot
        } else {
            og[k] = 0u;
            v[k]  = 0xFFFFFFFFu;
        }
    }
    #pragma unroll
    for (int s = 2; s <= 32 * R; s <<= 1) {
        #pragma unroll
        for (int d = (32 * R) >> 1; d >= 1; d >>= 1) {
            if (d >= s) continue;
            if (d >= 32) {
                int dd = d >> 5;
                #pragma unroll
                for (int k = 0; k < R; k++) {
                    if ((k & dd) == 0) {
                        int kh = k | dd;
                        bool up = (((k * 32 + lane) & s) == 0);
                        if ((v[k] > v[kh]) == up) { uint32_t t = v[k]; v[k] = v[kh]; v[kh] = t; }
                    }
                }
            } else {
                #pragma unroll
                for (int k = 0; k < R; k++) {
                    int p = k * 32 + lane;
                    bool up = ((p & s) == 0);
                    uint32_t o = __shfl_xor_sync(FULL, v[k], d);
                    bool lower = ((lane & d) == 0);
                    uint32_t mn = v[k] < o ? v[k] : o;
                    uint32_t mx = v[k] < o ? o : v[k];
                    v[k] = (up == lower) ? mn : mx;
                }
            }
        }
    }
    int carry = 0;
    #pragma unroll
    for (int k = 0; k < R; k++) {
        int p = k * 32 + lane;
        uint32_t pv = __shfl_up_sync(FULL, v[k], 1);
        uint32_t wrap = (k > 0) ? __shfl_sync(FULL, v[(k > 0) ? k - 1 : 0], 31)
                                : 0xFFFFFFFFu;
        if (lane == 0) pv = wrap;
        int f = 0;
        if (p < n) f = (p == 0) ? 1 : ((v[k] >> 8) != (pv >> 8));
        unsigned bal = __ballot_sync(FULL, f);
        rk[k] = carry + __popc(bal & (0xFFFFFFFFu >> (31 - lane)));
        fl[k] = f;
        carry += __popc(bal);
    }
    return carry;
}

template <int R>
__device__ __forceinline__ void row_phase2(int n, int lane, int rowbase,
                                           const uint32_t v[4], const uint32_t og[4],
                                           const int rk[4], const int fl[4]) {
    const unsigned FULL = 0xFFFFFFFFu;
    #pragma unroll
    for (int k = 0; k < R; k++) {
        int p = k * 32 + lane;
        uint32_t slot = v[k] & 0xFFu;
        uint32_t o0 = __shfl_sync(FULL, og[0], slot & 31);
        uint32_t o1 = (R > 1) ? __shfl_sync(FULL, og[1], slot & 31) : 0u;
        uint32_t o2 = (R > 2) ? __shfl_sync(FULL, og[2], slot & 31) : 0u;
        uint32_t o3 = (R > 3) ? __shfl_sync(FULL, og[3], slot & 31) : 0u;
        uint32_t r5 = slot >> 5;
        uint32_t orig = (r5 == 0) ? o0 : (r5 == 1) ? o1 : (r5 == 2) ? o2 : o3;
        if (p < n)
            g_segflag[orig] = ((uint32_t)(rowbase + rk[k] - 1) << 1) | (uint32_t)fl[k];
    }
}

// 2. 16 rows per 512-thread block; warp-per-row; warp-parallel lookback.
__global__ void __launch_bounds__(512)
k_rowsort() {
    const unsigned FULL = 0xFFFFFFFFu;
    __shared__ int s_bid;
    __shared__ int s_u[ROWS_PER_BLK];
    __shared__ int s_uex[ROWS_PER_BLK];
    __shared__ int s_excl;
    int tid = threadIdx.x, lane = tid & 31, wid = tid >> 5;
    if (tid == 0) s_bid = atomicAdd(&g_blkctr, 1);
    __syncthreads();
    const int bid = s_bid;
    const int row = bid * ROWS_PER_BLK + wid;
    int n = min(g_cnt[row], CAP);
    const unsigned long long* eb = g_bucket + (size_t)row * CAP;

    uint32_t v[4], og[4];
    int rk[4], fl[4];
    int u = 0;
    int mode = (n == 0) ? -1 : (n <= 64) ? 0 : 1;
    if (mode == 0)      u = row_phase1<2>(eb, n, lane, v, og, rk, fl);
    else if (mode == 1) u = row_phase1<4>(eb, n, lane, v, og, rk, fl);

    if (lane == 0) s_u[wid] = u;
    __syncthreads();

    if (wid == 0) {
        int val  = (lane < ROWS_PER_BLK) ? s_u[lane] : 0;
        int incl = val;
        #pragma unroll
        for (int d = 1; d < ROWS_PER_BLK; d <<= 1) {
            int nb = __shfl_up_sync(FULL, incl, d);
            if (lane >= d) incl += nb;
        }
        if (lane < ROWS_PER_BLK) s_uex[lane] = incl - val;
        int agg = __shfl_sync(FULL, incl, ROWS_PER_BLK - 1);

        int excl = 0;
        if (bid == 0) {
            if (lane == 0)
                atomicExch(&g_desc[0], (((unsigned long long)agg) << 2) | 2ull);
        } else {
            if (lane == 0)
                atomicExch(&g_desc[bid], (((unsigned long long)agg) << 2) | 1ull);
            __syncwarp();
            int jtop = bid - 1;
            while (true) {
                int idx = jtop - lane;
                unsigned long long d; unsigned st;
                if (idx >= 0) { d = atomicAdd(&g_desc[idx], 0ull); st = (unsigned)(d & 3ull); }
                else          { d = 2ull; st = 2u; }      // virtual prefix 0
                unsigned pref = __ballot_sync(FULL, st == 2u);
                unsigned nrdy = __ballot_sync(FULL, st == 0u);
                if (pref) {
                    int lp = __ffs(pref) - 1;
                    if ((nrdy & ((lp ? ((1u << lp) - 1u) : 0u))) == 0) {
                        int contrib = (lane <= lp) ? (int)(d >> 2) : 0;
                        #pragma unroll
                        for (int o = 16; o; o >>= 1)
                            contrib += __shfl_down_sync(FULL, contrib, o);
                        excl += __shfl_sync(FULL, contrib, 0);
                        break;
                    }
                } else if (!nrdy) {
                    int contrib = (int)(d >> 2);
                    #pragma unroll
                    for (int o = 16; o; o >>= 1)
                        contrib += __shfl_down_sync(FULL, contrib, o);
                    excl += __shfl_sync(FULL, contrib, 0);
                    jtop -= 32;
                    continue;
                }
                __nanosleep(20);
            }
            if (lane == 0)
                atomicExch(&g_desc[bid],
                           (((unsigned long long)(excl + agg)) << 2) | 2ull);
        }
        if (lane == 0) {
            s_excl = excl;
            if (bid == NBLK_D - 1) g_nu = excl + agg;
        }
    }
    __syncthreads();
    const int rowbase = s_excl + s_uex[wid];

    if (mode == 0)      row_phase2<2>(n, lane, rowbase, v, og, rk, fl);
    else if (mode == 1) row_phase2<4>(n, lane, rowbase, v, og, rk, fl);
}

// 3. fused: arrwp projection pipeline, then raw-edge copy, then tail pad.
//    CHUNK=128, blockDim=128 -> 36.8KB smem -> 6 blocks/SM (vs 2 at R8).
static constexpr int SM_FLAG = 16;
static constexpr int SM_ROW  = SM_FLAG + 2 * CHUNK * 4;   // 1040
static constexpr int SM_COL  = SM_ROW  + 2 * CHUNK * 4;   // 2064
static constexpr int SM_ATTR = 4096;
static constexpr int SM_TOTAL = SM_ATTR + 2 * CHUNK * 128;  // 36864

__global__ void __launch_bounds__(128, 6)
k_fused(const int* __restrict__ ei, const float* __restrict__ eattr,
        const int* __restrict__ ai, const float* __restrict__ aattr,
        const float* __restrict__ W, float* __restrict__ out,
        int Ee, int Ea) {
    extern __shared__ unsigned char sm[];
    const uint32_t sbase = smem_u32(sm);
    const int E = Ee + Ea;
    float* out_attr = out + 2 * (size_t)E;

    const int tid  = threadIdx.x;
    const int lane = tid & 31;
    const int wrp  = tid >> 5;

    // ---- section A: arrwp projection (double-buffered bulk-async pipeline)
    unsigned long long wa[16], wb[16];
    {
        const unsigned long long* Wa =
            reinterpret_cast<const unsigned long long*>(W + lane * 32);
        const unsigned long long* Wb =
            reinterpret_cast<const unsigned long long*>(W + (lane + 32) * 32);
        #pragma unroll
        for (int kk = 0; kk < 16; kk++) { wa[kk] = __ldg(Wa + kk); wb[kk] = __ldg(Wb + kk); }
    }

    const int nChunks = (Ea + CHUNK - 1) / CHUNK;
    if (tid == 0) { mbar_init(sbase + 0, 1); mbar_init(sbase + 8, 1); }
    __syncthreads();

    auto issue = [&](int c, int s) {
        int base = c * CHUNK;
        int rem  = min(CHUNK, Ea - base);
        bool full = (rem == CHUNK);
        uint32_t attrB = (uint32_t)rem * 128u;
        uint32_t flagB = ((uint32_t)rem * 4u + 15u) & ~15u;
        uint32_t tx = attrB + flagB + (full ? (uint32_t)(2 * CHUNK * 4) : 0u);
        uint32_t mb = sbase + s * 8;
        mbar_expect_tx(mb, tx);
        bulk_copy(sbase + SM_ATTR + s * (CHUNK * 128), aattr + (size_t)base * 32, attrB, mb);
        bulk_copy(sbase + SM_FLAG + s * (CHUNK * 4), &g_segflag[Ee + base], flagB, mb);
        if (full) {
            bulk_copy(sbase + SM_ROW + s * (CHUNK * 4), ai + base,      CHUNK * 4, mb);
            bulk_copy(sbase + SM_COL + s * (CHUNK * 4), ai + Ea + base, CHUNK * 4, mb);
        }
    };

    int c0 = blockIdx.x;
    if (c0 < nChunks) {
        if (tid == 0) issue(c0, 0);
        int phase0 = 0, phase1 = 0;
        int li = 0;
        for (int c = c0; c < nChunks; c += gridDim.x, li++) {
            int s = li & 1;
            int cn = c + gridDim.x;
            if (tid == 0 && cn < nChunks) issue(cn, s ^ 1);

            mbar_wait(sbase + s * 8, s ? phase1 : phase0);
            if (s) phase1 ^= 1; else phase0 ^= 1;

            int base = c * CHUNK;
            int rem  = min(CHUNK, Ea - base);
            bool full = (rem == CHUNK);
            int lbase = wrp * 32;
            if (lbase < rem) {
                int cnt = min(32, rem - lbase);
                const uint32_t* flag_s = (const uint32_t*)(sm + SM_FLAG + s * (CHUNK * 4));
                const int* row_s = (const int*)(sm + SM_ROW + s * (CHUNK * 4));
                const int* col_s = (const int*)(sm + SM_COL + s * (CHUNK * 4));
                const float* attr_s = (const float*)(sm + SM_ATTR + s * (CHUNK * 128));

                uint32_t sfv = (lane < cnt) ? flag_s[lbase + lane] : 0u;
                int rv = 0, cv = 0;
                if (full) { rv = row_s[lbase + lane]; cv = col_s[lbase + lane]; }

                for (int t = 0; t < cnt; t++) {
                    uint32_t sfe = __shfl_sync(0xFFFFFFFFu, sfv, t);
                    int rr = full ? __shfl_sync(0xFFFFFFFFu, rv, t) : 0;
                    int cc = full ? __shfl_sync(0xFFFFFFFFu, cv, t) : 0;
                    if (!(sfe & 1u)) continue;
                    int seg = (int)(sfe >> 1);
                    const unsigned long long* a2 =
                        (const unsigned long long*)(attr_s + (lbase + t) * 32);
                    // 4 accumulators: halve the serial FMA dependency depth
                    unsigned long long accA0 = 0ull, accA1 = 0ull;
                    unsigned long long accB0 = 0ull, accB1 = 0ull;
                    #pragma unroll
                    for (int kk = 0; kk < 8; kk++) {
                        unsigned long long av0 = a2[2 * kk];
                        unsigned long long av1 = a2[2 * kk + 1];
                        fma2(accA0, av0, wa[2 * kk]);
                        fma2(accA1, av1, wa[2 * kk + 1]);
                        fma2(accB0, av0, wb[2 * kk]);
                        fma2(accB1, av1, wb[2 * kk + 1]);
                    }
                    float a0x, a0y, a1x, a1y, b0x, b0y, b1x, b1y;
                    asm("mov.b64 {%0, %1}, %2;" : "=f"(a0x), "=f"(a0y) : "l"(accA0));
                    asm("mov.b64 {%0, %1}, %2;" : "=f"(a1x), "=f"(a1y) : "l"(accA1));
                    asm("mov.b64 {%0, %1}, %2;" : "=f"(b0x), "=f"(b0y) : "l"(accB0));
                    asm("mov.b64 {%0, %1}, %2;" : "=f"(b1x), "=f"(b1y) : "l"(accB1));
                    float* orow = out_attr + (size_t)seg * 64;
                    orow[lane]      = (a0x + a1x) + (a0y + a1y);
                    orow[32 + lane] = (b0x + b1x) + (b0y + b1y);
                    if (!full && lane == 0) {
                        int j = base + lbase + t;
                        rr = ai[j]; cc = ai[Ea + j];
                    }
                    if (lane == 0) {
                        out[seg]     = (float)rr;
                        out[E + seg] = (float)cc;
                    }
                }
            }
            __syncthreads();
        }
    }

    // ---- section B: raw-edge copy (grid-stride, one thread per float4)
    {
        const int gtid   = blockIdx.x * blockDim.x + tid;
        const int stride = gridDim.x * blockDim.x;
        const float4* eattr4 = reinterpret_cast<const float4*>(eattr);
        float4* out_attr4 = reinterpret_cast<float4*>(out_attr);
        const int total = Ee * 16;
        #pragma unroll 4
        for (int i = gtid; i < total; i += stride) {
            int e = i >> 4, f4 = i & 15;
            uint32_t sf = g_segflag[e];
            if (!(sf & 1u)) continue;
            int seg = (int)(sf >> 1);
            out_attr4[(size_t)seg * 16 + f4] = eattr4[i];
            if (f4 == 0) {
                out[seg]     = (float)ei[e];
                out[E + seg] = (float)ei[Ee + e];
            }
        }
    }

    // ---- section C: tail pad [nu, E)
    {
        const int nu = g_nu;
        const int gtid   = blockIdx.x * blockDim.x + tid;
        const int stride = gridDim.x * blockDim.x;
        for (int i = nu + gtid; i < E; i += stride) {
            out[i]     = -1.0f;
            out[E + i] = -1.0f;
        }
        size_t start = (size_t)nu * 64;
        size_t end   = (size_t)E * 64;
        for (size_t i = start + gtid; i < end; i += (size_t)stride)
            out_attr[i] = 0.0f;
        if (gtid == 0)
            out[2 * (size_t)E + (size_t)E * 64] = (float)nu;
    }
}

// 4. duplicate scatter: rare; runs AFTER the fused kernel (stream order).
__global__ void k_scatter_dups(const float* __restrict__ eattr,
                               const float* __restrict__ aattr,
                               const float* __restrict__ W,
                               float* __restrict__ out, int Ee, int Ea) {
    int E = Ee + Ea;
    int e = blockIdx.x * blockDim.x + threadIdx.x;
    if (e >= E) return;
    uint32_t sf = g_segflag[e];
    if (sf & 1u) return;
    int seg = (int)(sf >> 1);
    float* orow = out + 2 * (size_t)E + (size_t)seg * 64;
    if (e < Ee) {
        const float* a = eattr + (size_t)e * 64;
        for (int j = 0; j < 64; j++) atomicAdd(orow + j, a[j]);
    } else {
        const float* a = aattr + (size_t)(e - Ee) * 32;
        float av[32];
        #pragma unroll
        for (int k = 0; k < 32; k++) av[k] = a[k];
        for (int j = 0; j < 64; j++) {
            float s = 0.f;
            #pragma unroll
            for (int k = 0; k < 32; k++) s += av[k] * W[j * 32 + k];
            atomicAdd(orow + j, s);
        }
    }
}

// ---------------------------------------------------------------------------
extern "C" void kernel_launch(void* const* d_in, const int* in_sizes, int n_in,
                              void* d_out, int out_size) {
    (void)n_in; (void)out_size;
    const int*   ei    = (const int*)d_in[0];
    const float* eattr = (const float*)d_in[1];
    const int*   ai    = (const int*)d_in[2];
    const float* aattr = (const float*)d_in[3];
    const float* W     = (const float*)d_in[4];
    const int Ee = in_sizes[0] / 2;
    const int Ea = in_sizes[2] / 2;
    const int E  = Ee + Ea;
    float* out = (float*)d_out;

    static bool attr_set = false;
    if (!attr_set) {
        cudaFuncSetAttribute(k_fused,
                             cudaFuncAttributeMaxDynamicSharedMemorySize, SM_TOTAL);
        attr_set = true;
    }

    const int T = 256;
    k_init<<<(NROWS + T - 1) / T, T>>>();
    k_bucket<<<(E + T - 1) / T, T>>>(ei, ai, Ee, Ea);
    k_rowsort<<<NBLK_D, 512>>>();
    k_fused<<<FUSED_GRID, 128, SM_TOTAL>>>(ei, eattr, ai, aattr, W, out, Ee, Ea);
    k_scatter_dups<<<(E + T - 1) / T, T>>>(eattr, aattr, W, out, Ee, Ea);
}

// round 10
// speedup vs baseline: 1.3567x; 1.3567x over previous
#include <cuda_runtime.h>
#include <cstdint>

static constexpr int MAX_E = 1600000;             // < 2^21 (orig id fits 21 bits)
static constexpr int NROWS = 65536;               // row ids < 2^16
static constexpr int CAP   = 128;                 // slots per row bucket
static constexpr int ROWS_PER_BLK = 16;
static constexpr int NBLK_D = NROWS / ROWS_PER_BLK;  // 4096
static constexpr int CHUNK = 256;                 // arrwp rows per pipeline stage
static constexpr int FUSED_GRID = 444;            // 148 SMs x 3 blocks

// Scratch (allocation-free: __device__ globals)
__device__ unsigned long long g_bucket[(size_t)NROWS * CAP];  // (col<<32)|orig
__device__ int g_cnt[NROWS];
__device__ uint32_t g_segflag[MAX_E];             // per ORIGINAL edge: (seg<<1)|leader
__device__ unsigned long long g_desc[NBLK_D];     // lookback: (value<<2)|state
__device__ int g_blkctr;
__device__ int g_nu;

// ---------------------------------------------------------------------------
__device__ __forceinline__ uint32_t smem_u32(const void* p) {
    uint32_t a;
    asm("{ .reg .u64 t; cvta.to.shared.u64 t, %1; cvt.u32.u64 %0, t; }"
        : "=r"(a) : "l"(p));
    return a;
}
__device__ __forceinline__ void fma2(unsigned long long& acc,
                                     unsigned long long a, unsigned long long b) {
    asm("fma.rn.f32x2 %0, %1, %2, %0;" : "+l"(acc) : "l"(a), "l"(b));
}
__device__ __forceinline__ void mbar_init(uint32_t mbar, uint32_t cnt) {
    asm volatile("mbarrier.init.shared.b64 [%0], %1;" :: "r"(mbar), "r"(cnt) : "memory");
}
__device__ __forceinline__ void mbar_expect_tx(uint32_t mbar, uint32_t bytes) {
    asm volatile("mbarrier.arrive.expect_tx.shared.b64 _, [%0], %1;"
                 :: "r"(mbar), "r"(bytes) : "memory");
}
__device__ __forceinline__ void mbar_wait(uint32_t mbar, uint32_t parity) {
    uint32_t done;
    asm volatile(
        "{ .reg .pred p; mbarrier.try_wait.parity.acquire.cta.shared::cta.b64 p, [%1], %2;"
        " selp.b32 %0, 1, 0, p; }"
        : "=r"(done) : "r"(mbar), "r"(parity) : "memory");
    if (!done) {
        asm volatile(
            "{ .reg .pred P1; WL%=:"
            " mbarrier.try_wait.parity.acquire.cta.shared::cta.b64 P1, [%0], %1, 0x989680;"
            " @P1 bra.uni WD%=; bra.uni WL%=; WD%=: }"
            :: "r"(mbar), "r"(parity) : "memory");
    }
}
__device__ __forceinline__ void bulk_copy(uint32_t dst, const void* src,
                                          uint32_t bytes, uint32_t mbar) {
    asm volatile(
        "cp.async.bulk.shared::cta.global.mbarrier::complete_tx::bytes [%0], [%1], %2, [%3];"
        :: "r"(dst), "l"(src), "r"(bytes), "r"(mbar) : "memory");
}

// ---------------------------------------------------------------------------
// 0. per-launch reset
__global__ void k_init() {
    int i = blockIdx.x * blockDim.x + threadIdx.x;
    if (i < NROWS) g_cnt[i] = 0;
    if (i < NBLK_D) g_desc[i] = 0ull;
    if (i == 0) g_blkctr = 0;
}

// 1. bucket scatter: g_bucket[row*CAP + slot] = (col<<32)|orig
__global__ void k_bucket(const int* __restrict__ ei, const int* __restrict__ ai,
                         int Ee, int Ea) {
    int E = Ee + Ea;
    int i = blockIdx.x * blockDim.x + threadIdx.x;
    if (i >= E) return;
    int row, col;
    if (i < Ee) { row = ei[i];          col = ei[Ee + i]; }
    else        { int j = i - Ee; row = ai[j]; col = ai[Ea + j]; }
    int slot = atomicAdd(&g_cnt[row], 1);
    if (slot < CAP)
        g_bucket[(size_t)row * CAP + slot] =
            ((unsigned long long)(uint32_t)col << 32) | (unsigned long long)i;
}

// --- per-row machinery: u32 bitonic (size-adapted), flags, ranks ------------
template <int R>
__device__ __forceinline__ int row_phase1(const unsigned long long* __restrict__ eb,
                                          int n, int lane,
                                          uint32_t v[4], uint32_t og[4],
                                          int rk[4], int fl[4]) {
    const unsigned FULL = 0xFFFFFFFFu;
    #pragma unroll
    for (int k = 0; k < R; k++) {
        int p = k * 32 + lane;
        if (p < n) {
            unsigned long long e = eb[p];
            og[k] = (uint32_t)e;
            v[k]  = ((uint32_t)(e >> 32) << 8) | (uint32_t)p;  // (col<<8)|slot
        } else {
            og[k] = 0u;
            v[k]  = 0xFFFFFFFFu;
        }
    }
    #pragma unroll
    for (int s = 2; s <= 32 * R; s <<= 1) {
        #pragma unroll
        for (int d = (32 * R) >> 1; d >= 1; d >>= 1) {
            if (d >= s) continue;
            if (d >= 32) {
                int dd = d >> 5;
                #pragma unroll
                for (int k = 0; k < R; k++) {
                    if ((k & dd) == 0) {
                        int kh = k | dd;
                        bool up = (((k * 32 + lane) & s) == 0);
                        if ((v[k] > v[kh]) == up) { uint32_t t = v[k]; v[k] = v[kh]; v[kh] = t; }
                    }
                }
            } else {
                #pragma unroll
                for (int k = 0; k < R; k++) {
                    int p = k * 32 + lane;
                    bool up = ((p & s) == 0);
                    uint32_t o = __shfl_xor_sync(FULL, v[k], d);
                    bool lower = ((lane & d) == 0);
                    uint32_t mn = v[k] < o ? v[k] : o;
                    uint32_t mx = v[k] < o ? o : v[k];
                    v[k] = (up == lower) ? mn : mx;
                }
            }
        }
    }
    int carry = 0;
    #pragma unroll
    for (int k = 0; k < R; k++) {
        int p = k * 32 + lane;
        uint32_t pv = __shfl_up_sync(FULL, v[k], 1);
        uint32_t wrap = (k > 0) ? __shfl_sync(FULL, v[(k > 0) ? k - 1 : 0], 31)
                                : 0xFFFFFFFFu;
        if (lane == 0) pv = wrap;
        int f = 0;
        if (p < n) f = (p == 0) ? 1 : ((v[k] >> 8) != (pv >> 8));
        unsigned bal = __ballot_sync(FULL, f);
        rk[k] = carry + __popc(bal & (0xFFFFFFFFu >> (31 - lane)));
        fl[k] = f;
        carry += __popc(bal);
    }
    return carry;
}

template <int R>
__device__ __forceinline__ void row_phase2(int n, int lane, int rowbase,
                                           const uint32_t v[4], const uint32_t og[4],
                                           const int rk[4], const int fl[4]) {
    const unsigned FULL = 0xFFFFFFFFu;
    #pragma unroll
    for (int k = 0; k < R; k++) {
        int p = k * 32 + lane;
        uint32_t slot = v[k] & 0xFFu;
        uint32_t o0 = __shfl_sync(FULL, og[0], slot & 31);
        uint32_t o1 = (R > 1) ? __shfl_sync(FULL, og[1], slot & 31) : 0u;
        uint32_t o2 = (R > 2) ? __shfl_sync(FULL, og[2], slot & 31) : 0u;
        uint32_t o3 = (R > 3) ? __shfl_sync(FULL, og[3], slot & 31) : 0u;
        uint32_t r5 = slot >> 5;
        uint32_t orig = (r5 == 0) ? o0 : (r5 == 1) ? o1 : (r5 == 2) ? o2 : o3;
        if (p < n)
            g_segflag[orig] = ((uint32_t)(rowbase + rk[k] - 1) << 1) | (uint32_t)fl[k];
    }
}

// 2. 16 rows per 512-thread block; warp-per-row; warp-parallel lookback.
__global__ void __launch_bounds__(512)
k_rowsort() {
    const unsigned FULL = 0xFFFFFFFFu;
    __shared__ int s_bid;
    __shared__ int s_u[ROWS_PER_BLK];
    __shared__ int s_uex[ROWS_PER_BLK];
    __shared__ int s_excl;
    int tid = threadIdx.x, lane = tid & 31, wid = tid >> 5;
    if (tid == 0) s_bid = atomicAdd(&g_blkctr, 1);
    __syncthreads();
    const int bid = s_bid;
    const int row = bid * ROWS_PER_BLK + wid;
    int n = min(g_cnt[row], CAP);
    const unsigned long long* eb = g_bucket + (size_t)row * CAP;

    uint32_t v[4], og[4];
    int rk[4], fl[4];
    int u = 0;
    int mode = (n == 0) ? -1 : (n <= 64) ? 0 : 1;
    if (mode == 0)      u = row_phase1<2>(eb, n, lane, v, og, rk, fl);
    else if (mode == 1) u = row_phase1<4>(eb, n, lane, v, og, rk, fl);

    if (lane == 0) s_u[wid] = u;
    __syncthreads();

    if (wid == 0) {
        int val  = (lane < ROWS_PER_BLK) ? s_u[lane] : 0;
        int incl = val;
        #pragma unroll
        for (int d = 1; d < ROWS_PER_BLK; d <<= 1) {
            int nb = __shfl_up_sync(FULL, incl, d);
            if (lane >= d) incl += nb;
        }
        if (lane < ROWS_PER_BLK) s_uex[lane] = incl - val;
        int agg = __shfl_sync(FULL, incl, ROWS_PER_BLK - 1);

        int excl = 0;
        if (bid == 0) {
            if (lane == 0)
                atomicExch(&g_desc[0], (((unsigned long long)agg) << 2) | 2ull);
        } else {
            if (lane == 0)
                atomicExch(&g_desc[bid], (((unsigned long long)agg) << 2) | 1ull);
            __syncwarp();
            int jtop = bid - 1;
            while (true) {
                int idx = jtop - lane;
                unsigned long long d; unsigned st;
                if (idx >= 0) { d = atomicAdd(&g_desc[idx], 0ull); st = (unsigned)(d & 3ull); }
                else          { d = 2ull; st = 2u; }      // virtual prefix 0
                unsigned pref = __ballot_sync(FULL, st == 2u);
                unsigned nrdy = __ballot_sync(FULL, st == 0u);
                if (pref) {
                    int lp = __ffs(pref) - 1;
                    if ((nrdy & ((lp ? ((1u << lp) - 1u) : 0u))) == 0) {
                        int contrib = (lane <= lp) ? (int)(d >> 2) : 0;
                        #pragma unroll
                        for (int o = 16; o; o >>= 1)
                            contrib += __shfl_down_sync(FULL, contrib, o);
                        excl += __shfl_sync(FULL, contrib, 0);
                        break;
                    }
                } else if (!nrdy) {
                    int contrib = (int)(d >> 2);
                    #pragma unroll
                    for (int o = 16; o; o >>= 1)
                        contrib += __shfl_down_sync(FULL, contrib, o);
                    excl += __shfl_sync(FULL, contrib, 0);
                    jtop -= 32;
                    continue;
                }
                __nanosleep(20);
            }
            if (lane == 0)
                atomicExch(&g_desc[bid],
                           (((unsigned long long)(excl + agg)) << 2) | 2ull);
        }
        if (lane == 0) {
            s_excl = excl;
            if (bid == NBLK_D - 1) g_nu = excl + agg;
        }
    }
    __syncthreads();
    const int rowbase = s_excl + s_uex[wid];

    if (mode == 0)      row_phase2<2>(n, lane, rowbase, v, og, rk, fl);
    else if (mode == 1) row_phase2<4>(n, lane, rowbase, v, og, rk, fl);
}

// 3. fused: arrwp projection pipeline, then raw-edge copy, then tail pad.
//    Warp-pair mapping: lane owns ONE output col (half*32+lane); W = 32 regs.
//    256 threads, 3 blocks/SM (85-reg cap; est. ~70 regs -> no spill).
static constexpr int SM_FLAG = 16;
static constexpr int SM_ROW  = SM_FLAG + 2 * CHUNK * 4;
static constexpr int SM_COL  = SM_ROW  + 2 * CHUNK * 4;
static constexpr int SM_ATTR = 8192;
static constexpr int SM_TOTAL = SM_ATTR + 2 * CHUNK * 128;  // 73728

__global__ void __launch_bounds__(256, 3)
k_fused(const int* __restrict__ ei, const float* __restrict__ eattr,
        const int* __restrict__ ai, const float* __restrict__ aattr,
        const float* __restrict__ W, float* __restrict__ out,
        int Ee, int Ea) {
    extern __shared__ unsigned char sm[];
    const uint32_t sbase = smem_u32(sm);
    const int E = Ee + Ea;
    float* out_attr = out + 2 * (size_t)E;

    const int tid  = threadIdx.x;
    const int lane = tid & 31;
    const int wrp  = tid >> 5;
    const int grp  = wrp >> 1;        // 0..3: edge group within chunk
    const int half = wrp & 1;         // 0/1: which 32 output cols

    // ---- section A: arrwp projection (double-buffered bulk-async pipeline)
    // per-lane W: single col j = half*32+lane, packed float2 over k-pairs
    unsigned long long w2[16];
    {
        const unsigned long long* Wj =
            reinterpret_cast<const unsigned long long*>(W + (half * 32 + lane) * 32);
        #pragma unroll
        for (int kk = 0; kk < 16; kk++) w2[kk] = __ldg(Wj + kk);
    }

    const int nChunks = (Ea + CHUNK - 1) / CHUNK;
    if (tid == 0) { mbar_init(sbase + 0, 1); mbar_init(sbase + 8, 1); }
    __syncthreads();

    auto issue = [&](int c, int s) {
        int base = c * CHUNK;
        int rem  = min(CHUNK, Ea - base);
        bool full = (rem == CHUNK);
        uint32_t attrB = (uint32_t)rem * 128u;
        uint32_t flagB = ((uint32_t)rem * 4u + 15u) & ~15u;
        uint32_t tx = attrB + flagB + (full ? (uint32_t)(2 * CHUNK * 4) : 0u);
        uint32_t mb = sbase + s * 8;
        mbar_expect_tx(mb, tx);
        bulk_copy(sbase + SM_ATTR + s * (CHUNK * 128), aattr + (size_t)base * 32, attrB, mb);
        bulk_copy(sbase + SM_FLAG + s * (CHUNK * 4), &g_segflag[Ee + base], flagB, mb);
        if (full) {
            bulk_copy(sbase + SM_ROW + s * (CHUNK * 4), ai + base,      CHUNK * 4, mb);
            bulk_copy(sbase + SM_COL + s * (CHUNK * 4), ai + Ea + base, CHUNK * 4, mb);
        }
    };

    int c0 = blockIdx.x;
    if (c0 < nChunks) {
        if (tid == 0) issue(c0, 0);
        int phase0 = 0, phase1 = 0;
        int li = 0;
        for (int c = c0; c < nChunks; c += gridDim.x, li++) {
            int s = li & 1;
            int cn = c + gridDim.x;
            if (tid == 0 && cn < nChunks) issue(cn, s ^ 1);

            mbar_wait(sbase + s * 8, s ? phase1 : phase0);
            if (s) phase1 ^= 1; else phase0 ^= 1;

            int base = c * CHUNK;
            int rem  = min(CHUNK, Ea - base);
            bool full = (rem == CHUNK);
            int lbase = grp * 64;                  // 64 edges per warp-pair
            if (lbase < rem) {
                int cnt = min(64, rem - lbase);
                const uint32_t* flag_s = (const uint32_t*)(sm + SM_FLAG + s * (CHUNK * 4));
                const int* row_s = (const int*)(sm + SM_ROW + s * (CHUNK * 4));
                const int* col_s = (const int*)(sm + SM_COL + s * (CHUNK * 4));
                const float* attr_s = (const float*)(sm + SM_ATTR + s * (CHUNK * 128));

                for (int t = 0; t < cnt; t++) {
                    uint32_t sfe = flag_s[lbase + t];      // uniform LDS
                    if (!(sfe & 1u)) continue;             // non-leader (rare)
                    int seg = (int)(sfe >> 1);
                    const unsigned long long* a2 =
                        (const unsigned long long*)(attr_s + (lbase + t) * 32);
                    unsigned long long acc0 = 0ull, acc1 = 0ull;
                    #pragma unroll
                    for (int kk = 0; kk < 8; kk++) {
                        unsigned long long av0 = a2[2 * kk];      // uniform LDS.64
                        unsigned long long av1 = a2[2 * kk + 1];
                        fma2(acc0, av0, w2[2 * kk]);
                        fma2(acc1, av1, w2[2 * kk + 1]);
                    }
                    float x0, y0, x1, y1;
                    asm("mov.b64 {%0, %1}, %2;" : "=f"(x0), "=f"(y0) : "l"(acc0));
                    asm("mov.b64 {%0, %1}, %2;" : "=f"(x1), "=f"(y1) : "l"(acc1));
                    out_attr[(size_t)seg * 64 + half * 32 + lane] =
                        (x0 + x1) + (y0 + y1);
                    if (half == 0 && lane == 0) {
                        int rr, cc;
                        if (full) { rr = row_s[lbase + t]; cc = col_s[lbase + t]; }
                        else      { int j = base + lbase + t; rr = ai[j]; cc = ai[Ea + j]; }
                        out[seg]     = (float)rr;
                        out[E + seg] = (float)cc;
                    }
                }
            }
            __syncthreads();
        }
    }

    // ---- section B: raw-edge copy (grid-stride, one thread per float4)
    {
        const int gtid   = blockIdx.x * blockDim.x + tid;
        const int stride = gridDim.x * blockDim.x;
        const float4* eattr4 = reinterpret_cast<const float4*>(eattr);
        float4* out_attr4 = reinterpret_cast<float4*>(out_attr);
        const int total = Ee * 16;
        for (int i = gtid; i < total; i += stride) {
            int e = i >> 4, f4 = i & 15;
            uint32_t sf = g_segflag[e];
            if (!(sf & 1u)) continue;
            int seg = (int)(sf >> 1);
            out_attr4[(size_t)seg * 16 + f4] = eattr4[i];
            if (f4 == 0) {
                out[seg]     = (float)ei[e];
                out[E + seg] = (float)ei[Ee + e];
            }
        }
    }

    // ---- section C: tail pad [nu, E)
    {
        const int nu = g_nu;
        const int gtid   = blockIdx.x * blockDim.x + tid;
        const int stride = gridDim.x * blockDim.x;
        for (int i = nu + gtid; i < E; i += stride) {
            out[i]     = -1.0f;
            out[E + i] = -1.0f;
        }
        size_t start = (size_t)nu * 64;
        size_t end   = (size_t)E * 64;
        for (size_t i = start + gtid; i < end; i += (size_t)stride)
            out_attr[i] = 0.0f;
        if (gtid == 0)
            out[2 * (size_t)E + (size_t)E * 64] = (float)nu;
    }
}

// 4. duplicate scatter: rare; runs AFTER the fused kernel (stream order).
__global__ void k_scatter_dups(const float* __restrict__ eattr,
                               const float* __restrict__ aattr,
                               const float* __restrict__ W,
                               float* __restrict__ out, int Ee, int Ea) {
    int E = Ee + Ea;
    int e = blockIdx.x * blockDim.x + threadIdx.x;
    if (e >= E) return;
    uint32_t sf = g_segflag[e];
    if (sf & 1u) return;
    int seg = (int)(sf >> 1);
    float* orow = out + 2 * (size_t)E + (size_t)seg * 64;
    if (e < Ee) {
        const float* a = eattr + (size_t)e * 64;
        for (int j = 0; j < 64; j++) atomicAdd(orow + j, a[j]);
    } else {
        const float* a = aattr + (size_t)(e - Ee) * 32;
        float av[32];
        #pragma unroll
        for (int k = 0; k < 32; k++) av[k] = a[k];
        for (int j = 0; j < 64; j++) {
            float s = 0.f;
            #pragma unroll
            for (int k = 0; k < 32; k++) s += av[k] * W[j * 32 + k];
            atomicAdd(orow + j, s);
        }
    }
}

// ---------------------------------------------------------------------------
extern "C" void kernel_launch(void* const* d_in, const int* in_sizes, int n_in,
                              void* d_out, int out_size) {
    (void)n_in; (void)out_size;
    const int*   ei    = (const int*)d_in[0];
    const float* eattr = (const float*)d_in[1];
    const int*   ai    = (const int*)d_in[2];
    const float* aattr = (const float*)d_in[3];
    const float* W     = (const float*)d_in[4];
    const int Ee = in_sizes[0] / 2;
    const int Ea = in_sizes[2] / 2;
    const int E  = Ee + Ea;
    float* out = (float*)d_out;

    static bool attr_set = false;
    if (!attr_set) {
        cudaFuncSetAttribute(k_fused,
                             cudaFuncAttributeMaxDynamicSharedMemorySize, SM_TOTAL);
        attr_set = true;
    }

    const int T = 256;
    k_init<<<(NROWS + T - 1) / T, T>>>();
    k_bucket<<<(E + T - 1) / T, T>>>(ei, ai, Ee, Ea);
    k_rowsort<<<NBLK_D, 512>>>();
    k_fused<<<FUSED_GRID, 256, SM_TOTAL>>>(ei, eattr, ai, aattr, W, out, Ee, Ea);
    k_scatter_dups<<<(E + T - 1) / T, T>>>(eattr, aattr, W, out, Ee, Ea);
}

// round 11
// speedup vs baseline: 1.4033x; 1.0344x over previous
#include <cuda_runtime.h>
#include <cstdint>

static constexpr int MAX_E = 1600000;             // < 2^21 (orig id fits 21 bits)
static constexpr int NROWS = 65536;               // row ids < 2^16
static constexpr int CAP   = 128;                 // slots per row bucket
static constexpr int ROWS_PER_BLK = 16;
static constexpr int NBLK_D = NROWS / ROWS_PER_BLK;  // 4096
static constexpr int CHUNK = 256;                 // arrwp rows per pipeline stage
static constexpr int FUSED_GRID = 444;            // 148 SMs x 3 blocks

// Scratch (allocation-free: __device__ globals)
__device__ unsigned long long g_bucket[(size_t)NROWS * CAP];  // (col<<32)|orig
__device__ int g_cnt[NROWS];
__device__ uint32_t g_segflag[MAX_E];             // per ORIGINAL edge: (seg<<1)|leader
__device__ unsigned long long g_desc[NBLK_D];     // lookback: (value<<2)|state
__device__ int g_blkctr;
__device__ int g_nu;

// ---------------------------------------------------------------------------
__device__ __forceinline__ uint32_t smem_u32(const void* p) {
    uint32_t a;
    asm("{ .reg .u64 t; cvta.to.shared.u64 t, %1; cvt.u32.u64 %0, t; }"
        : "=r"(a) : "l"(p));
    return a;
}
__device__ __forceinline__ void fma2(unsigned long long& acc,
                                     unsigned long long a, unsigned long long b) {
    asm("fma.rn.f32x2 %0, %1, %2, %0;" : "+l"(acc) : "l"(a), "l"(b));
}
__device__ __forceinline__ float merge2(unsigned long long a, unsigned long long b) {
    unsigned long long s;
    asm("add.rn.f32x2 %0, %1, %2;" : "=l"(s) : "l"(a), "l"(b));
    float x, y;
    asm("mov.b64 {%0, %1}, %2;" : "=f"(x), "=f"(y) : "l"(s));
    return x + y;
}
__device__ __forceinline__ void mbar_init(uint32_t mbar, uint32_t cnt) {
    asm volatile("mbarrier.init.shared.b64 [%0], %1;" :: "r"(mbar), "r"(cnt) : "memory");
}
__device__ __forceinline__ void mbar_expect_tx(uint32_t mbar, uint32_t bytes) {
    asm volatile("mbarrier.arrive.expect_tx.shared.b64 _, [%0], %1;"
                 :: "r"(mbar), "r"(bytes) : "memory");
}
__device__ __forceinline__ void mbar_wait(uint32_t mbar, uint32_t parity) {
    uint32_t done;
    asm volatile(
        "{ .reg .pred p; mbarrier.try_wait.parity.acquire.cta.shared::cta.b64 p, [%1], %2;"
        " selp.b32 %0, 1, 0, p; }"
        : "=r"(done) : "r"(mbar), "r"(parity) : "memory");
    if (!done) {
        asm volatile(
            "{ .reg .pred P1; WL%=:"
            " mbarrier.try_wait.parity.acquire.cta.shared::cta.b64 P1, [%0], %1, 0x989680;"
            " @P1 bra.uni WD%=; bra.uni WL%=; WD%=: }"
            :: "r"(mbar), "r"(parity) : "memory");
    }
}
__device__ __forceinline__ void bulk_copy(uint32_t dst, const void* src,
                                          uint32_t bytes, uint32_t mbar) {
    asm volatile(
        "cp.async.bulk.shared::cta.global.mbarrier::complete_tx::bytes [%0], [%1], %2, [%3];"
        :: "r"(dst), "l"(src), "r"(bytes), "r"(mbar) : "memory");
}

// ---------------------------------------------------------------------------
// 0. per-launch reset
__global__ void k_init() {
    int i = blockIdx.x * blockDim.x + threadIdx.x;
    if (i < NROWS) g_cnt[i] = 0;
    if (i < NBLK_D) g_desc[i] = 0ull;
    if (i == 0) g_blkctr = 0;
}

// 1. bucket scatter: g_bucket[row*CAP + slot] = (col<<32)|orig
__global__ void k_bucket(const int* __restrict__ ei, const int* __restrict__ ai,
                         int Ee, int Ea) {
    int E = Ee + Ea;
    int i = blockIdx.x * blockDim.x + threadIdx.x;
    if (i >= E) return;
    int row, col;
    if (i < Ee) { row = ei[i];          col = ei[Ee + i]; }
    else        { int j = i - Ee; row = ai[j]; col = ai[Ea + j]; }
    int slot = atomicAdd(&g_cnt[row], 1);
    if (slot < CAP)
        g_bucket[(size_t)row * CAP + slot] =
            ((unsigned long long)(uint32_t)col << 32) | (unsigned long long)i;
}

// --- per-row machinery: u32 bitonic (size-adapted), flags, ranks ------------
template <int R>
__device__ __forceinline__ int row_phase1(const unsigned long long* __restrict__ eb,
                                          int n, int lane,
                                          uint32_t v[4], uint32_t og[4],
                                          int rk[4], int fl[4]) {
    const unsigned FULL = 0xFFFFFFFFu;
    #pragma unroll
    for (int k = 0; k < R; k++) {
        int p = k * 32 + lane;
        if (p < n) {
            unsigned long long e = eb[p];
            og[k] = (uint32_t)e;
            v[k]  = ((uint32_t)(e >> 32) << 8) | (uint32_t)p;  // (col<<8)|slot
        } else {
            og[k] = 0u;
            v[k]  = 0xFFFFFFFFu;
        }
    }
    #pragma unroll
    for (int s = 2; s <= 32 * R; s <<= 1) {
        #pragma unroll
        for (int d = (32 * R) >> 1; d >= 1; d >>= 1) {
            if (d >= s) continue;
            if (d >= 32) {
                int dd = d >> 5;
                #pragma unroll
                for (int k = 0; k < R; k++) {
                    if ((k & dd) == 0) {
                        int kh = k | dd;
                        bool up = (((k * 32 + lane) & s) == 0);
                        if ((v[k] > v[kh]) == up) { uint32_t t = v[k]; v[k] = v[kh]; v[kh] = t; }
                    }
                }
            } else {
                #pragma unroll
                for (int k = 0; k < R; k++) {
                    int p = k * 32 + lane;
                    bool up = ((p & s) == 0);
                    uint32_t o = __shfl_xor_sync(FULL, v[k], d);
                    bool lower = ((lane & d) == 0);
                    uint32_t mn = v[k] < o ? v[k] : o;
                    uint32_t mx = v[k] < o ? o : v[k];
                    v[k] = (up == lower) ? mn : mx;
                }
            }
        }
    }
    int carry = 0;
    #pragma unroll
    for (int k = 0; k < R; k++) {
        int p = k * 32 + lane;
        uint32_t pv = __shfl_up_sync(FULL, v[k], 1);
        uint32_t wrap = (k > 0) ? __shfl_sync(FULL, v[(k > 0) ? k - 1 : 0], 31)
                                : 0xFFFFFFFFu;
        if (lane == 0) pv = wrap;
        int f = 0;
        if (p < n) f = (p == 0) ? 1 : ((v[k] >> 8) != (pv >> 8));
        unsigned bal = __ballot_sync(FULL, f);
        rk[k] = carry + __popc(bal & (0xFFFFFFFFu >> (31 - lane)));
        fl[k] = f;
        carry += __popc(bal);
    }
    return carry;
}

template <int R>
__device__ __forceinline__ void row_phase2(int n, int lane, int rowbase,
                                           const uint32_t v[4], const uint32_t og[4],
                                           const int rk[4], const int fl[4]) {
    const unsigned FULL = 0xFFFFFFFFu;
    #pragma unroll
    for (int k = 0; k < R; k++) {
        int p = k * 32 + lane;
        uint32_t slot = v[k] & 0xFFu;
        uint32_t o0 = __shfl_sync(FULL, og[0], slot & 31);
        uint32_t o1 = (R > 1) ? __shfl_sync(FULL, og[1], slot & 31) : 0u;
        uint32_t o2 = (R > 2) ? __shfl_sync(FULL, og[2], slot & 31) : 0u;
        uint32_t o3 = (R > 3) ? __shfl_sync(FULL, og[3], slot & 31) : 0u;
        uint32_t r5 = slot >> 5;
        uint32_t orig = (r5 == 0) ? o0 : (r5 == 1) ? o1 : (r5 == 2) ? o2 : o3;
        if (p < n)
            g_segflag[orig] = ((uint32_t)(rowbase + rk[k] - 1) << 1) | (uint32_t)fl[k];
    }
}

// 2. 16 rows per 512-thread block; warp-per-row; warp-parallel lookback.
__global__ void __launch_bounds__(512)
k_rowsort() {
    const unsigned FULL = 0xFFFFFFFFu;
    __shared__ int s_bid;
    __shared__ int s_u[ROWS_PER_BLK];
    __shared__ int s_uex[ROWS_PER_BLK];
    __shared__ int s_excl;
    int tid = threadIdx.x, lane = tid & 31, wid = tid >> 5;
    if (tid == 0) s_bid = atomicAdd(&g_blkctr, 1);
    __syncthreads();
    const int bid = s_bid;
    const int row = bid * ROWS_PER_BLK + wid;
    int n = min(g_cnt[row], CAP);
    const unsigned long long* eb = g_bucket + (size_t)row * CAP;

    uint32_t v[4], og[4];
    int rk[4], fl[4];
    int u = 0;
    int mode = (n == 0) ? -1 : (n <= 64) ? 0 : 1;
    if (mode == 0)      u = row_phase1<2>(eb, n, lane, v, og, rk, fl);
    else if (mode == 1) u = row_phase1<4>(eb, n, lane, v, og, rk, fl);

    if (lane == 0) s_u[wid] = u;
    __syncthreads();

    if (wid == 0) {
        int val  = (lane < ROWS_PER_BLK) ? s_u[lane] : 0;
        int incl = val;
        #pragma unroll
        for (int d = 1; d < ROWS_PER_BLK; d <<= 1) {
            int nb = __shfl_up_sync(FULL, incl, d);
            if (lane >= d) incl += nb;
        }
        if (lane < ROWS_PER_BLK) s_uex[lane] = incl - val;
        int agg = __shfl_sync(FULL, incl, ROWS_PER_BLK - 1);

        int excl = 0;
        if (bid == 0) {
            if (lane == 0)
                atomicExch(&g_desc[0], (((unsigned long long)agg) << 2) | 2ull);
        } else {
            if (lane == 0)
                atomicExch(&g_desc[bid], (((unsigned long long)agg) << 2) | 1ull);
            __syncwarp();
            int jtop = bid - 1;
            while (true) {
                int idx = jtop - lane;
                unsigned long long d; unsigned st;
                if (idx >= 0) { d = atomicAdd(&g_desc[idx], 0ull); st = (unsigned)(d & 3ull); }
                else          { d = 2ull; st = 2u; }      // virtual prefix 0
                unsigned pref = __ballot_sync(FULL, st == 2u);
                unsigned nrdy = __ballot_sync(FULL, st == 0u);
                if (pref) {
                    int lp = __ffs(pref) - 1;
                    if ((nrdy & ((lp ? ((1u << lp) - 1u) : 0u))) == 0) {
                        int contrib = (lane <= lp) ? (int)(d >> 2) : 0;
                        #pragma unroll
                        for (int o = 16; o; o >>= 1)
                            contrib += __shfl_down_sync(FULL, contrib, o);
                        excl += __shfl_sync(FULL, contrib, 0);
                        break;
                    }
                } else if (!nrdy) {
                    int contrib = (int)(d >> 2);
                    #pragma unroll
                    for (int o = 16; o; o >>= 1)
                        contrib += __shfl_down_sync(FULL, contrib, o);
                    excl += __shfl_sync(FULL, contrib, 0);
                    jtop -= 32;
                    continue;
                }
                __nanosleep(20);
            }
            if (lane == 0)
                atomicExch(&g_desc[bid],
                           (((unsigned long long)(excl + agg)) << 2) | 2ull);
        }
        if (lane == 0) {
            s_excl = excl;
            if (bid == NBLK_D - 1) g_nu = excl + agg;
        }
    }
    __syncthreads();
    const int rowbase = s_excl + s_uex[wid];

    if (mode == 0)      row_phase2<2>(n, lane, rowbase, v, og, rk, fl);
    else if (mode == 1) row_phase2<4>(n, lane, rowbase, v, og, rk, fl);
}

// 3. fused: arrwp projection pipeline, then raw-edge copy, then tail pad.
//    Warp-pair mapping (lane owns ONE output col); 2-edge interleaved inner
//    loop with LDS.128 attr loads (4 independent FMA chains).
static constexpr int SM_FLAG = 16;
static constexpr int SM_ROW  = SM_FLAG + 2 * CHUNK * 4;
static constexpr int SM_COL  = SM_ROW  + 2 * CHUNK * 4;
static constexpr int SM_ATTR = 8192;
static constexpr int SM_TOTAL = SM_ATTR + 2 * CHUNK * 128;  // 73728

__global__ void __launch_bounds__(256, 3)
k_fused(const int* __restrict__ ei, const float* __restrict__ eattr,
        const int* __restrict__ ai, const float* __restrict__ aattr,
        const float* __restrict__ W, float* __restrict__ out,
        int Ee, int Ea) {
    extern __shared__ unsigned char sm[];
    const uint32_t sbase = smem_u32(sm);
    const int E = Ee + Ea;
    float* out_attr = out + 2 * (size_t)E;

    const int tid  = threadIdx.x;
    const int lane = tid & 31;
    const int wrp  = tid >> 5;
    const int grp  = wrp >> 1;        // 0..3: edge group within chunk
    const int half = wrp & 1;         // 0/1: which 32 output cols

    // ---- section A: arrwp projection (double-buffered bulk-async pipeline)
    unsigned long long w2[16];
    {
        const unsigned long long* Wj =
            reinterpret_cast<const unsigned long long*>(W + (half * 32 + lane) * 32);
        #pragma unroll
        for (int kk = 0; kk < 16; kk++) w2[kk] = __ldg(Wj + kk);
    }

    const int nChunks = (Ea + CHUNK - 1) / CHUNK;
    if (tid == 0) { mbar_init(sbase + 0, 1); mbar_init(sbase + 8, 1); }
    __syncthreads();

    auto issue = [&](int c, int s) {
        int base = c * CHUNK;
        int rem  = min(CHUNK, Ea - base);
        bool full = (rem == CHUNK);
        uint32_t attrB = (uint32_t)rem * 128u;
        uint32_t flagB = ((uint32_t)rem * 4u + 15u) & ~15u;
        uint32_t tx = attrB + flagB + (full ? (uint32_t)(2 * CHUNK * 4) : 0u);
        uint32_t mb = sbase + s * 8;
        mbar_expect_tx(mb, tx);
        bulk_copy(sbase + SM_ATTR + s * (CHUNK * 128), aattr + (size_t)base * 32, attrB, mb);
        bulk_copy(sbase + SM_FLAG + s * (CHUNK * 4), &g_segflag[Ee + base], flagB, mb);
        if (full) {
            bulk_copy(sbase + SM_ROW + s * (CHUNK * 4), ai + base,      CHUNK * 4, mb);
            bulk_copy(sbase + SM_COL + s * (CHUNK * 4), ai + Ea + base, CHUNK * 4, mb);
        }
    };

    int c0 = blockIdx.x;
    if (c0 < nChunks) {
        if (tid == 0) issue(c0, 0);
        int phase0 = 0, phase1 = 0;
        int li = 0;
        for (int c = c0; c < nChunks; c += gridDim.x, li++) {
            int s = li & 1;
            int cn = c + gridDim.x;
            if (tid == 0 && cn < nChunks) issue(cn, s ^ 1);

            mbar_wait(sbase + s * 8, s ? phase1 : phase0);
            if (s) phase1 ^= 1; else phase0 ^= 1;

            int base = c * CHUNK;
            int rem  = min(CHUNK, Ea - base);
            bool full = (rem == CHUNK);
            int lbase = grp * 64;                  // 64 edges per warp-pair
            if (lbase < rem) {
                int cnt = min(64, rem - lbase);
                const uint32_t* flag_s = (const uint32_t*)(sm + SM_FLAG + s * (CHUNK * 4));
                const int* row_s = (const int*)(sm + SM_ROW + s * (CHUNK * 4));
                const int* col_s = (const int*)(sm + SM_COL + s * (CHUNK * 4));
                const float* attr_s = (const float*)(sm + SM_ATTR + s * (CHUNK * 128));

                auto store_edge = [&](int t, uint32_t sfe, float val) {
                    int seg = (int)(sfe >> 1);
                    out_attr[(size_t)seg * 64 + half * 32 + lane] = val;
                    if (half == 0 && lane == 0) {
                        int rr, cc;
                        if (full) { rr = row_s[lbase + t]; cc = col_s[lbase + t]; }
                        else      { int j = base + lbase + t; rr = ai[j]; cc = ai[Ea + j]; }
                        out[seg]     = (float)rr;
                        out[E + seg] = (float)cc;
                    }
                };

                int cnt2 = cnt & ~1;
                for (int t = 0; t < cnt2; t += 2) {
                    uint2 ff = *reinterpret_cast<const uint2*>(flag_s + lbase + t);
                    const ulonglong2* A0 =
                        (const ulonglong2*)(attr_s + (lbase + t) * 32);
                    const ulonglong2* A1 =
                        (const ulonglong2*)(attr_s + (lbase + t + 1) * 32);
                    unsigned long long a00 = 0ull, a01 = 0ull;
                    unsigned long long a10 = 0ull, a11 = 0ull;
                    #pragma unroll
                    for (int q = 0; q < 8; q++) {
                        ulonglong2 p0 = A0[q];           // uniform LDS.128
                        ulonglong2 p1 = A1[q];
                        fma2(a00, p0.x, w2[2 * q]);
                        fma2(a01, p0.y, w2[2 * q + 1]);
                        fma2(a10, p1.x, w2[2 * q]);
                        fma2(a11, p1.y, w2[2 * q + 1]);
                    }
                    if (ff.x & 1u) store_edge(t,     ff.x, merge2(a00, a01));
                    if (ff.y & 1u) store_edge(t + 1, ff.y, merge2(a10, a11));
                }
                if (cnt & 1) {
                    int t = cnt2;
                    uint32_t sfe = flag_s[lbase + t];
                    if (sfe & 1u) {
                        const ulonglong2* A0 =
                            (const ulonglong2*)(attr_s + (lbase + t) * 32);
                        unsigned long long a00 = 0ull, a01 = 0ull;
                        #pragma unroll
                        for (int q = 0; q < 8; q++) {
                            ulonglong2 p0 = A0[q];
                            fma2(a00, p0.x, w2[2 * q]);
                            fma2(a01, p0.y, w2[2 * q + 1]);
                        }
                        store_edge(t, sfe, merge2(a00, a01));
                    }
                }
            }
            __syncthreads();
        }
    }

    // ---- section B: raw-edge copy (grid-stride, 2 float4 per thread)
    {
        const int gtid   = blockIdx.x * blockDim.x + tid;
        const int stride = gridDim.x * blockDim.x;
        const float4* eattr4 = reinterpret_cast<const float4*>(eattr);
        float4* out_attr4 = reinterpret_cast<float4*>(out_attr);
        const int total = Ee * 8;                  // 8 x 32B per edge
        for (int i = gtid; i < total; i += stride) {
            int e = i >> 3, h = (i & 7) * 2;
            uint32_t sf = g_segflag[e];
            if (!(sf & 1u)) continue;
            int seg = (int)(sf >> 1);
            float4 v0 = eattr4[(size_t)e * 16 + h];
            float4 v1 = eattr4[(size_t)e * 16 + h + 1];
            out_attr4[(size_t)seg * 16 + h]     = v0;
            out_attr4[(size_t)seg * 16 + h + 1] = v1;
            if (h == 0) {
                out[seg]     = (float)ei[e];
                out[E + seg] = (float)ei[Ee + e];
            }
        }
    }

    // ---- section C: tail pad [nu, E)
    {
        const int nu = g_nu;
        const int gtid   = blockIdx.x * blockDim.x + tid;
        const int stride = gridDim.x * blockDim.x;
        for (int i = nu + gtid; i < E; i += stride) {
            out[i]     = -1.0f;
            out[E + i] = -1.0f;
        }
        size_t start = (size_t)nu * 64;
        size_t end   = (size_t)E * 64;
        for (size_t i = start + gtid; i < end; i += (size_t)stride)
            out_attr[i] = 0.0f;
        if (gtid == 0)
            out[2 * (size_t)E + (size_t)E * 64] = (float)nu;
    }
}

// 4. duplicate scatter: rare; runs AFTER the fused kernel (stream order).
__global__ void k_scatter_dups(const float* __restrict__ eattr,
                               const float* __restrict__ aattr,
                               const float* __restrict__ W,
                               float* __restrict__ out, int Ee, int Ea) {
    int E = Ee + Ea;
    int e = blockIdx.x * blockDim.x + threadIdx.x;
    if (e >= E) return;
    uint32_t sf = g_segflag[e];
    if (sf & 1u) return;
    int seg = (int)(sf >> 1);
    float* orow = out + 2 * (size_t)E + (size_t)seg * 64;
    if (e < Ee) {
        const float* a = eattr + (size_t)e * 64;
        for (int j = 0; j < 64; j++) atomicAdd(orow + j, a[j]);
    } else {
        const float* a = aattr + (size_t)(e - Ee) * 32;
        float av[32];
        #pragma unroll
        for (int k = 0; k < 32; k++) av[k] = a[k];
        for (int j = 0; j < 64; j++) {
            float s = 0.f;
            #pragma unroll
            for (int k = 0; k < 32; k++) s += av[k] * W[j * 32 + k];
            atomicAdd(orow + j, s);
        }
    }
}

// ---------------------------------------------------------------------------
extern "C" void kernel_launch(void* const* d_in, const int* in_sizes, int n_in,
                              void* d_out, int out_size) {
    (void)n_in; (void)out_size;
    const int*   ei    = (const int*)d_in[0];
    const float* eattr = (const float*)d_in[1];
    const int*   ai    = (const int*)d_in[2];
    const float* aattr = (const float*)d_in[3];
    const float* W     = (const float*)d_in[4];
    const int Ee = in_sizes[0] / 2;
    const int Ea = in_sizes[2] / 2;
    const int E  = Ee + Ea;
    float* out = (float*)d_out;

    static bool attr_set = false;
    if (!attr_set) {
        cudaFuncSetAttribute(k_fused,
                             cudaFuncAttributeMaxDynamicSharedMemorySize, SM_TOTAL);
        attr_set = true;
    }

    const int T = 256;
    k_init<<<(NROWS + T - 1) / T, T>>>();
    k_bucket<<<(E + T - 1) / T, T>>>(ei, ai, Ee, Ea);
    k_rowsort<<<NBLK_D, 512>>>();
    k_fused<<<FUSED_GRID, 256, SM_TOTAL>>>(ei, eattr, ai, aattr, W, out, Ee, Ea);
    k_scatter_dups<<<(E + T - 1) / T, T>>>(eattr, aattr, W, out, Ee, Ea);
}

// round 13
// speedup vs baseline: 1.6520x; 1.1772x over previous
#include <cuda_runtime.h>
#include <cstdint>

static constexpr int MAX_E = 1600000;             // < 2^21 (ids fit 21 bits)
static constexpr int NROWS = 65536;               // row ids < 2^16
static constexpr int CAP   = 128;                 // slots per row bucket
static constexpr int ROWS_PER_BLK = 16;
static constexpr int NBLK_D = NROWS / ROWS_PER_BLK;  // 4096
static constexpr int CHUNK = 256;                 // arrwp rows per pipeline stage
static constexpr int FUSED_GRID = 444;            // 148 SMs x 3 blocks

// Scratch (allocation-free: __device__ globals)
__device__ unsigned long long g_bucket[(size_t)NROWS * CAP];  // (col<<32)|orig
__device__ int g_cnt[NROWS];
__device__ uint32_t g_segflag[MAX_E];             // per ORIGINAL edge: (seg<<1)|leader
__device__ unsigned long long g_desc[NBLK_D];     // lookback: (value<<2)|state
__device__ unsigned long long g_duplist[MAX_E];   // (seg<<21)|orig for duplicates
__device__ int g_dupcnt;
__device__ int g_blkctr;
__device__ int g_nu;

// ---------------------------------------------------------------------------
__device__ __forceinline__ uint32_t smem_u32(const void* p) {
    uint32_t a;
    asm("{ .reg .u64 t; cvta.to.shared.u64 t, %1; cvt.u32.u64 %0, t; }"
        : "=r"(a) : "l"(p));
    return a;
}
__device__ __forceinline__ void fma2(unsigned long long& acc,
                                     unsigned long long a, unsigned long long b) {
    asm("fma.rn.f32x2 %0, %1, %2, %0;" : "+l"(acc) : "l"(a), "l"(b));
}
__device__ __forceinline__ float merge2(unsigned long long a, unsigned long long b) {
    unsigned long long s;
    asm("add.rn.f32x2 %0, %1, %2;" : "=l"(s) : "l"(a), "l"(b));
    float x, y;
    asm("mov.b64 {%0, %1}, %2;" : "=f"(x), "=f"(y) : "l"(s));
    return x + y;
}
__device__ __forceinline__ void mbar_init(uint32_t mbar, uint32_t cnt) {
    asm volatile("mbarrier.init.shared.b64 [%0], %1;" :: "r"(mbar), "r"(cnt) : "memory");
}
__device__ __forceinline__ void mbar_expect_tx(uint32_t mbar, uint32_t bytes) {
    asm volatile("mbarrier.arrive.expect_tx.shared.b64 _, [%0], %1;"
                 :: "r"(mbar), "r"(bytes) : "memory");
}
__device__ __forceinline__ void mbar_wait(uint32_t mbar, uint32_t parity) {
    uint32_t done;
    asm volatile(
        "{ .reg .pred p; mbarrier.try_wait.parity.acquire.cta.shared::cta.b64 p, [%1], %2;"
        " selp.b32 %0, 1, 0, p; }"
        : "=r"(done) : "r"(mbar), "r"(parity) : "memory");
    if (!done) {
        asm volatile(
            "{ .reg .pred P1; WL%=:"
            " mbarrier.try_wait.parity.acquire.cta.shared::cta.b64 P1, [%0], %1, 0x989680;"
            " @P1 bra.uni WD%=; bra.uni WL%=; WD%=: }"
            :: "r"(mbar), "r"(parity) : "memory");
    }
}
__device__ __forceinline__ void bulk_copy(uint32_t dst, const void* src,
                                          uint32_t bytes, uint32_t mbar) {
    asm volatile(
        "cp.async.bulk.shared::cta.global.mbarrier::complete_tx::bytes [%0], [%1], %2, [%3];"
        :: "r"(dst), "l"(src), "r"(bytes), "r"(mbar) : "memory");
}

// ---------------------------------------------------------------------------
// 0. per-launch reset
__global__ void k_init() {
    int i = blockIdx.x * blockDim.x + threadIdx.x;
    if (i < NROWS) g_cnt[i] = 0;
    if (i < NBLK_D) g_desc[i] = 0ull;
    if (i == 0) { g_blkctr = 0; g_dupcnt = 0; }
}

// 1. bucket scatter: g_bucket[row*CAP + slot] = (col<<32)|orig
__global__ void k_bucket(const int* __restrict__ ei, const int* __restrict__ ai,
                         int Ee, int Ea) {
    int E = Ee + Ea;
    int i = blockIdx.x * blockDim.x + threadIdx.x;
    if (i >= E) return;
    int row, col;
    if (i < Ee) { row = ei[i];          col = ei[Ee + i]; }
    else        { int j = i - Ee; row = ai[j]; col = ai[Ea + j]; }
    int slot = atomicAdd(&g_cnt[row], 1);
    if (slot < CAP)
        g_bucket[(size_t)row * CAP + slot] =
            ((unsigned long long)(uint32_t)col << 32) | (unsigned long long)i;
}

// --- per-row machinery: u32 bitonic (size-adapted), flags, ranks ------------
template <int R>
__device__ __forceinline__ int row_phase1(const unsigned long long* __restrict__ eb,
                                          int n, int lane,
                                          uint32_t v[4], uint32_t og[4],
                                          int rk[4], int fl[4]) {
    const unsigned FULL = 0xFFFFFFFFu;
    #pragma unroll
    for (int k = 0; k < R; k++) {
        int p = k * 32 + lane;
        if (p < n) {
            unsigned long long e = eb[p];
            og[k] = (uint32_t)e;
            v[k]  = ((uint32_t)(e >> 32) << 8) | (uint32_t)p;  // (col<<8)|slot
        } else {
            og[k] = 0u;
            v[k]  = 0xFFFFFFFFu;
        }
    }
    #pragma unroll
    for (int s = 2; s <= 32 * R; s <<= 1) {
        #pragma unroll
        for (int d = (32 * R) >> 1; d >= 1; d >>= 1) {
            if (d >= s) continue;
            if (d >= 32) {
                int dd = d >> 5;
                #pragma unroll
                for (int k = 0; k < R; k++) {
                    if ((k & dd) == 0) {
                        int kh = k | dd;
                        bool up = (((k * 32 + lane) & s) == 0);
                        if ((v[k] > v[kh]) == up) { uint32_t t = v[k]; v[k] = v[kh]; v[kh] = t; }
                    }
                }
            } else {
                #pragma unroll
                for (int k = 0; k < R; k++) {
                    int p = k * 32 + lane;
                    bool up = ((p & s) == 0);
                    uint32_t o = __shfl_xor_sync(FULL, v[k], d);
                    bool lower = ((lane & d) == 0);
                    uint32_t mn = v[k] < o ? v[k] : o;
                    uint32_t mx = v[k] < o ? o : v[k];
                    v[k] = (up == lower) ? mn : mx;
                }
            }
        }
    }
    int carry = 0;
    #pragma unroll
    for (int k = 0; k < R; k++) {
        int p = k * 32 + lane;
        uint32_t pv = __shfl_up_sync(FULL, v[k], 1);
        uint32_t wrap = (k > 0) ? __shfl_sync(FULL, v[(k > 0) ? k - 1 : 0], 31)
                                : 0xFFFFFFFFu;
        if (lane == 0) pv = wrap;
        int f = 0;
        if (p < n) f = (p == 0) ? 1 : ((v[k] >> 8) != (pv >> 8));
        unsigned bal = __ballot_sync(FULL, f);
        rk[k] = carry + __popc(bal & (0xFFFFFFFFu >> (31 - lane)));
        fl[k] = f;
        carry += __popc(bal);
    }
    return carry;
}

// phase 2: scatter segflag[orig]; leaders also write out_r/out_c (seg-contig,
// streaming); non-leaders append to the duplicate worklist.
template <int R>
__device__ __forceinline__ void row_phase2(int n, int lane, int rowbase, int row,
                                           float* __restrict__ out, int E,
                                           const uint32_t v[4], const uint32_t og[4],
                                           const int rk[4], const int fl[4]) {
    const unsigned FULL = 0xFFFFFFFFu;
    #pragma unroll
    for (int k = 0; k < R; k++) {
        int p = k * 32 + lane;
        uint32_t slot = v[k] & 0xFFu;
        uint32_t o0 = __shfl_sync(FULL, og[0], slot & 31);
        uint32_t o1 = (R > 1) ? __shfl_sync(FULL, og[1], slot & 31) : 0u;
        uint32_t o2 = (R > 2) ? __shfl_sync(FULL, og[2], slot & 31) : 0u;
        uint32_t o3 = (R > 3) ? __shfl_sync(FULL, og[3], slot & 31) : 0u;
        uint32_t r5 = slot >> 5;
        uint32_t orig = (r5 == 0) ? o0 : (r5 == 1) ? o1 : (r5 == 2) ? o2 : o3;
        if (p < n) {
            int seg = rowbase + rk[k] - 1;
            g_segflag[orig] = ((uint32_t)seg << 1) | (uint32_t)fl[k];
            if (fl[k]) {
                out[seg]     = (float)row;
                out[E + seg] = (float)(v[k] >> 8);
            } else {
                int di = atomicAdd(&g_dupcnt, 1);
                g_duplist[di] = ((unsigned long long)(uint32_t)seg << 21)
                              | (unsigned long long)orig;
            }
        }
    }
}

// 2. 16 rows per 512-thread block; warp-per-row; warp-parallel lookback.
__global__ void __launch_bounds__(512)
k_rowsort(float* __restrict__ out, int E) {
    const unsigned FULL = 0xFFFFFFFFu;
    __shared__ int s_bid;
    __shared__ int s_u[ROWS_PER_BLK];
    __shared__ int s_uex[ROWS_PER_BLK];
    __shared__ int s_excl;
    int tid = threadIdx.x, lane = tid & 31, wid = tid >> 5;
    if (tid == 0) s_bid = atomicAdd(&g_blkctr, 1);
    __syncthreads();
    const int bid = s_bid;
    const int row = bid * ROWS_PER_BLK + wid;
    int n = min(g_cnt[row], CAP);
    const unsigned long long* eb = g_bucket + (size_t)row * CAP;

    uint32_t v[4], og[4];
    int rk[4], fl[4];
    int u = 0;
    int mode = (n == 0) ? -1 : (n <= 64) ? 0 : 1;
    if (mode == 0)      u = row_phase1<2>(eb, n, lane, v, og, rk, fl);
    else if (mode == 1) u = row_phase1<4>(eb, n, lane, v, og, rk, fl);

    if (lane == 0) s_u[wid] = u;
    __syncthreads();

    if (wid == 0) {
        int val  = (lane < ROWS_PER_BLK) ? s_u[lane] : 0;
        int incl = val;
        #pragma unroll
        for (int d = 1; d < ROWS_PER_BLK; d <<= 1) {
            int nb = __shfl_up_sync(FULL, incl, d);
            if (lane >= d) incl += nb;
        }
        if (lane < ROWS_PER_BLK) s_uex[lane] = incl - val;
        int agg = __shfl_sync(FULL, incl, ROWS_PER_BLK - 1);

        int excl = 0;
        if (bid == 0) {
            if (lane == 0)
                atomicExch(&g_desc[0], (((unsigned long long)agg) << 2) | 2ull);
        } else {
            if (lane == 0)
                atomicExch(&g_desc[bid], (((unsigned long long)agg) << 2) | 1ull);
            __syncwarp();
            int jtop = bid - 1;
            while (true) {
                int idx = jtop - lane;
                unsigned long long d; unsigned st;
                if (idx >= 0) { d = atomicAdd(&g_desc[idx], 0ull); st = (unsigned)(d & 3ull); }
                else          { d = 2ull; st = 2u; }      // virtual prefix 0
                unsigned pref = __ballot_sync(FULL, st == 2u);
                unsigned nrdy = __ballot_sync(FULL, st == 0u);
                if (pref) {
                    int lp = __ffs(pref) - 1;
                    if ((nrdy & ((lp ? ((1u << lp) - 1u) : 0u))) == 0) {
                        int contrib = (lane <= lp) ? (int)(d >> 2) : 0;
                        #pragma unroll
                        for (int o = 16; o; o >>= 1)
                            contrib += __shfl_down_sync(FULL, contrib, o);
                        excl += __shfl_sync(FULL, contrib, 0);
                        break;
                    }
                } else if (!nrdy) {
                    int contrib = (int)(d >> 2);
                    #pragma unroll
                    for (int o = 16; o; o >>= 1)
                        contrib += __shfl_down_sync(FULL, contrib, o);
                    excl += __shfl_sync(FULL, contrib, 0);
                    jtop -= 32;
                    continue;
                }
                __nanosleep(20);
            }
            if (lane == 0)
                atomicExch(&g_desc[bid],
                           (((unsigned long long)(excl + agg)) << 2) | 2ull);
        }
        if (lane == 0) {
            s_excl = excl;
            if (bid == NBLK_D - 1) g_nu = excl + agg;
        }
    }
    __syncthreads();
    const int rowbase = s_excl + s_uex[wid];

    if (mode == 0)      row_phase2<2>(n, lane, rowbase, row, out, E, v, og, rk, fl);
    else if (mode == 1) row_phase2<4>(n, lane, rowbase, row, out, E, v, og, rk, fl);
}

// 3. fused: arrwp projection pipeline, then raw-edge attr copy, then tail pad.
//    (r/c written by rowsort; no row/col staging here anymore.)
static constexpr int SM_FLAG = 16;
static constexpr int SM_ATTR = 4096;              // flags fit below
static constexpr int SM_TOTAL = SM_ATTR + 2 * CHUNK * 128;  // 69632

__global__ void __launch_bounds__(256, 3)
k_fused(const float* __restrict__ eattr, const float* __restrict__ aattr,
        const float* __restrict__ W, float* __restrict__ out,
        int Ee, int Ea) {
    extern __shared__ unsigned char sm[];
    const uint32_t sbase = smem_u32(sm);
    const int E = Ee + Ea;
    float* out_attr = out + 2 * (size_t)E;

    const int tid  = threadIdx.x;
    const int lane = tid & 31;
    const int wrp  = tid >> 5;
    const int grp  = wrp >> 1;        // 0..3: edge group within chunk
    const int half = wrp & 1;         // 0/1: which 32 output cols

    // ---- section A: arrwp projection (double-buffered bulk-async pipeline)
    unsigned long long w2[16];
    {
        const unsigned long long* Wj =
            reinterpret_cast<const unsigned long long*>(W + (half * 32 + lane) * 32);
        #pragma unroll
        for (int kk = 0; kk < 16; kk++) w2[kk] = __ldg(Wj + kk);
    }

    const int nChunks = (Ea + CHUNK - 1) / CHUNK;
    if (tid == 0) { mbar_init(sbase + 0, 1); mbar_init(sbase + 8, 1); }
    __syncthreads();

    auto issue = [&](int c, int s) {
        int base = c * CHUNK;
        int rem  = min(CHUNK, Ea - base);
        uint32_t attrB = (uint32_t)rem * 128u;
        uint32_t flagB = ((uint32_t)rem * 4u + 15u) & ~15u;
        uint32_t mb = sbase + s * 8;
        mbar_expect_tx(mb, attrB + flagB);
        bulk_copy(sbase + SM_ATTR + s * (CHUNK * 128), aattr + (size_t)base * 32, attrB, mb);
        bulk_copy(sbase + SM_FLAG + s * (CHUNK * 4), &g_segflag[Ee + base], flagB, mb);
    };

    int c0 = blockIdx.x;
    if (c0 < nChunks) {
        if (tid == 0) issue(c0, 0);
        int phase0 = 0, phase1 = 0;
        int li = 0;
        for (int c = c0; c < nChunks; c += gridDim.x, li++) {
            int s = li & 1;
            int cn = c + gridDim.x;
            if (tid == 0 && cn < nChunks) issue(cn, s ^ 1);

            mbar_wait(sbase + s * 8, s ? phase1 : phase0);
            if (s) phase1 ^= 1; else phase0 ^= 1;

            int rem  = min(CHUNK, Ea - c * CHUNK);
            int lbase = grp * 64;                  // 64 edges per warp-pair
            if (lbase < rem) {
                int cnt = min(64, rem - lbase);
                const uint32_t* flag_s = (const uint32_t*)(sm + SM_FLAG + s * (CHUNK * 4));
                const float* attr_s = (const float*)(sm + SM_ATTR + s * (CHUNK * 128));

                int cnt2 = cnt & ~1;
                for (int t = 0; t < cnt2; t += 2) {
                    uint2 ff = *reinterpret_cast<const uint2*>(flag_s + lbase + t);
                    const ulonglong2* A0 =
                        (const ulonglong2*)(attr_s + (lbase + t) * 32);
                    const ulonglong2* A1 =
                        (const ulonglong2*)(attr_s + (lbase + t + 1) * 32);
                    unsigned long long a00 = 0ull, a01 = 0ull;
                    unsigned long long a10 = 0ull, a11 = 0ull;
                    #pragma unroll
                    for (int q = 0; q < 8; q++) {
                        ulonglong2 p0 = A0[q];           // uniform LDS.128
                        ulonglong2 p1 = A1[q];
                        fma2(a00, p0.x, w2[2 * q]);
                        fma2(a01, p0.y, w2[2 * q + 1]);
                        fma2(a10, p1.x, w2[2 * q]);
                        fma2(a11, p1.y, w2[2 * q + 1]);
                    }
                    if (ff.x & 1u)
                        out_attr[(size_t)(ff.x >> 1) * 64 + half * 32 + lane] =
                            merge2(a00, a01);
                    if (ff.y & 1u)
                        out_attr[(size_t)(ff.y >> 1) * 64 + half * 32 + lane] =
                            merge2(a10, a11);
                }
                if (cnt & 1) {
                    int t = cnt2;
                    uint32_t sfe = flag_s[lbase + t];
                    if (sfe & 1u) {
                        const ulonglong2* A0 =
                            (const ulonglong2*)(attr_s + (lbase + t) * 32);
                        unsigned long long a00 = 0ull, a01 = 0ull;
                        #pragma unroll
                        for (int q = 0; q < 8; q++) {
                            ulonglong2 p0 = A0[q];
                            fma2(a00, p0.x, w2[2 * q]);
                            fma2(a01, p0.y, w2[2 * q + 1]);
                        }
                        out_attr[(size_t)(sfe >> 1) * 64 + half * 32 + lane] =
                            merge2(a00, a01);
                    }
                }
            }
            __syncthreads();
        }
    }

    // ---- section B: raw-edge attr copy (grid-stride, 2 float4 per thread)
    {
        const int gtid   = blockIdx.x * blockDim.x + tid;
        const int stride = gridDim.x * blockDim.x;
        const float4* eattr4 = reinterpret_cast<const float4*>(eattr);
        float4* out_attr4 = reinterpret_cast<float4*>(out_attr);
        const int total = Ee * 8;                  // 8 x 32B per edge
        for (int i = gtid; i < total; i += stride) {
            int e = i >> 3, h = (i & 7) * 2;
            uint32_t sf = g_segflag[e];
            if (!(sf & 1u)) continue;
            int seg = (int)(sf >> 1);
            float4 v0 = eattr4[(size_t)e * 16 + h];
            float4 v1 = eattr4[(size_t)e * 16 + h + 1];
            out_attr4[(size_t)seg * 16 + h]     = v0;
            out_attr4[(size_t)seg * 16 + h + 1] = v1;
        }
    }

    // ---- section C: tail pad [nu, E)
    {
        const int nu = g_nu;
        const int gtid   = blockIdx.x * blockDim.x + tid;
        const int stride = gridDim.x * blockDim.x;
        for (int i = nu + gtid; i < E; i += stride) {
            out[i]     = -1.0f;
            out[E + i] = -1.0f;
        }
        size_t start = (size_t)nu * 64;
        size_t end   = (size_t)E * 64;
        for (size_t i = start + gtid; i < end; i += (size_t)stride)
            out_attr[i] = 0.0f;
        if (gtid == 0)
            out[2 * (size_t)E + (size_t)E * 64] = (float)nu;
    }
}

// 4. duplicate scatter: worklist-driven (~hundreds of entries); runs AFTER
//    the fused kernel (stream order).
__global__ void k_scatter_dups(const float* __restrict__ eattr,
                               const float* __restrict__ aattr,
                               const float* __restrict__ W,
                               float* __restrict__ out, int Ee, int Ea) {
    int E = Ee + Ea;
    int ndup = g_dupcnt;
    int stride = gridDim.x * blockDim.x;
    for (int i = blockIdx.x * blockDim.x + threadIdx.x; i < ndup; i += stride) {
        unsigned long long ent = g_duplist[i];
        int seg  = (int)(ent >> 21);
        int orig = (int)(ent & 0x1FFFFFull);
        float* orow = out + 2 * (size_t)E + (size_t)seg * 64;
        if (orig < Ee) {
            const float* a = eattr + (size_t)orig * 64;
            for (int j = 0; j < 64; j++) atomicAdd(orow + j, a[j]);
        } else {
            const float* a = aattr + (size_t)(orig - Ee) * 32;
            float av[32];
            #pragma unroll
            for (int k = 0; k < 32; k++) av[k] = a[k];
            for (int j = 0; j < 64; j++) {
                float s = 0.f;
                #pragma unroll
                for (int k = 0; k < 32; k++) s += av[k] * W[j * 32 + k];
                atomicAdd(orow + j, s);
            }
        }
    }
}

// ---------------------------------------------------------------------------
extern "C" void kernel_launch(void* const* d_in, const int* in_sizes, int n_in,
                              void* d_out, int out_size) {
    (void)n_in; (void)out_size;
    const int*   ei    = (const int*)d_in[0];
    const float* eattr = (const float*)d_in[1];
    const int*   ai    = (const int*)d_in[2];
    const float* aattr = (const float*)d_in[3];
    const float* W     = (const float*)d_in[4];
    const int Ee = in_sizes[0] / 2;
    const int Ea = in_sizes[2] / 2;
    const int E  = Ee + Ea;
    float* out = (float*)d_out;

    static bool attr_set = false;
    if (!attr_set) {
        cudaFuncSetAttribute(k_fused,
                             cudaFuncAttributeMaxDynamicSharedMemorySize, SM_TOTAL);
        attr_set = true;
    }

    const int T = 256;
    k_init<<<(NROWS + T - 1) / T, T>>>();
    k_bucket<<<(E + T - 1) / T, T>>>(ei, ai, Ee, Ea);
    k_rowsort<<<NBLK_D, 512>>>(out, E);
    k_fused<<<FUSED_GRID, 256, SM_TOTAL>>>(eattr, aattr, W, out, Ee, Ea);
    k_scatter_dups<<<64, T>>>(eattr, aattr, W, out, Ee, Ea);
}

// round 14
// speedup vs baseline: 1.6829x; 1.0187x over previous
#include <cuda_runtime.h>
#include <cstdint>

static constexpr int MAX_E = 1600000;             // < 2^21 (ids fit 21 bits)
static constexpr int NROWS = 65536;               // row ids < 2^16
static constexpr int CAP   = 128;                 // slots per row bucket
static constexpr int ROWS_PER_BLK = 16;
static constexpr int NBLK_D = NROWS / ROWS_PER_BLK;  // 4096
static constexpr int CHUNK = 256;                 // arrwp rows per pipeline stage
static constexpr int FUSED_GRID = 296;            // 148 SMs x 2 blocks

// Scratch (allocation-free: __device__ globals)
__device__ unsigned long long g_bucket[(size_t)NROWS * CAP];  // (col<<32)|orig
__device__ int g_cnt[NROWS];
__device__ uint32_t g_segflag[MAX_E];             // per ORIGINAL edge: (seg<<1)|leader
__device__ unsigned long long g_desc[NBLK_D];     // lookback: (value<<2)|state
__device__ unsigned long long g_duplist[MAX_E];   // (seg<<21)|orig for duplicates
__device__ int g_dupcnt;
__device__ int g_blkctr;
__device__ int g_nu;

// ---------------------------------------------------------------------------
__device__ __forceinline__ uint32_t smem_u32(const void* p) {
    uint32_t a;
    asm("{ .reg .u64 t; cvta.to.shared.u64 t, %1; cvt.u32.u64 %0, t; }"
        : "=r"(a) : "l"(p));
    return a;
}
__device__ __forceinline__ void fma2(unsigned long long& acc,
                                     unsigned long long a, unsigned long long b) {
    asm("fma.rn.f32x2 %0, %1, %2, %0;" : "+l"(acc) : "l"(a), "l"(b));
}
__device__ __forceinline__ float hsum2(unsigned long long a) {
    float x, y;
    asm("mov.b64 {%0, %1}, %2;" : "=f"(x), "=f"(y) : "l"(a));
    return x + y;
}
__device__ __forceinline__ void mbar_init(uint32_t mbar, uint32_t cnt) {
    asm volatile("mbarrier.init.shared.b64 [%0], %1;" :: "r"(mbar), "r"(cnt) : "memory");
}
__device__ __forceinline__ void mbar_expect_tx(uint32_t mbar, uint32_t bytes) {
    asm volatile("mbarrier.arrive.expect_tx.shared.b64 _, [%0], %1;"
                 :: "r"(mbar), "r"(bytes) : "memory");
}
__device__ __forceinline__ void mbar_wait(uint32_t mbar, uint32_t parity) {
    uint32_t done;
    asm volatile(
        "{ .reg .pred p; mbarrier.try_wait.parity.acquire.cta.shared::cta.b64 p, [%1], %2;"
        " selp.b32 %0, 1, 0, p; }"
        : "=r"(done) : "r"(mbar), "r"(parity) : "memory");
    if (!done) {
        asm volatile(
            "{ .reg .pred P1; WL%=:"
            " mbarrier.try_wait.parity.acquire.cta.shared::cta.b64 P1, [%0], %1, 0x989680;"
            " @P1 bra.uni WD%=; bra.uni WL%=; WD%=: }"
            :: "r"(mbar), "r"(parity) : "memory");
    }
}
__device__ __forceinline__ void bulk_copy(uint32_t dst, const void* src,
                                          uint32_t bytes, uint32_t mbar) {
    asm volatile(
        "cp.async.bulk.shared::cta.global.mbarrier::complete_tx::bytes [%0], [%1], %2, [%3];"
        :: "r"(dst), "l"(src), "r"(bytes), "r"(mbar) : "memory");
}

// ---------------------------------------------------------------------------
// 0. per-launch reset
__global__ void k_init() {
    int i = blockIdx.x * blockDim.x + threadIdx.x;
    if (i < NROWS) g_cnt[i] = 0;
    if (i < NBLK_D) g_desc[i] = 0ull;
    if (i == 0) { g_blkctr = 0; g_dupcnt = 0; }
}

// 1. bucket scatter: g_bucket[row*CAP + slot] = (col<<32)|orig
__global__ void k_bucket(const int* __restrict__ ei, const int* __restrict__ ai,
                         int Ee, int Ea) {
    int E = Ee + Ea;
    int i = blockIdx.x * blockDim.x + threadIdx.x;
    if (i >= E) return;
    int row, col;
    if (i < Ee) { row = ei[i];          col = ei[Ee + i]; }
    else        { int j = i - Ee; row = ai[j]; col = ai[Ea + j]; }
    int slot = atomicAdd(&g_cnt[row], 1);
    if (slot < CAP)
        g_bucket[(size_t)row * CAP + slot] =
            ((unsigned long long)(uint32_t)col << 32) | (unsigned long long)i;
}

// --- per-row machinery: u32 bitonic (size-adapted), flags, ranks ------------
template <int R>
__device__ __forceinline__ int row_phase1(const unsigned long long* __restrict__ eb,
                                          int n, int lane,
                                          uint32_t v[4], uint32_t og[4],
                                          int rk[4], int fl[4]) {
    const unsigned FULL = 0xFFFFFFFFu;
    #pragma unroll
    for (int k = 0; k < R; k++) {
        int p = k * 32 + lane;
        if (p < n) {
            unsigned long long e = eb[p];
            og[k] = (uint32_t)e;
            v[k]  = ((uint32_t)(e >> 32) << 8) | (uint32_t)p;  // (col<<8)|slot
        } else {
            og[k] = 0u;
            v[k]  = 0xFFFFFFFFu;
        }
    }
    #pragma unroll
    for (int s = 2; s <= 32 * R; s <<= 1) {
        #pragma unroll
        for (int d = (32 * R) >> 1; d >= 1; d >>= 1) {
            if (d >= s) continue;
            if (d >= 32) {
                int dd = d >> 5;
                #pragma unroll
                for (int k = 0; k < R; k++) {
                    if ((k & dd) == 0) {
                        int kh = k | dd;
                        bool up = (((k * 32 + lane) & s) == 0);
                        if ((v[k] > v[kh]) == up) { uint32_t t = v[k]; v[k] = v[kh]; v[kh] = t; }
                    }
                }
            } else {
                #pragma unroll
                for (int k = 0; k < R; k++) {
                    int p = k * 32 + lane;
                    bool up = ((p & s) == 0);
                    uint32_t o = __shfl_xor_sync(FULL, v[k], d);
                    bool lower = ((lane & d) == 0);
                    uint32_t mn = v[k] < o ? v[k] : o;
                    uint32_t mx = v[k] < o ? o : v[k];
                    v[k] = (up == lower) ? mn : mx;
                }
            }
        }
    }
    int carry = 0;
    #pragma unroll
    for (int k = 0; k < R; k++) {
        int p = k * 32 + lane;
        uint32_t pv = __shfl_up_sync(FULL, v[k], 1);
        uint32_t wrap = (k > 0) ? __shfl_sync(FULL, v[(k > 0) ? k - 1 : 0], 31)
                                : 0xFFFFFFFFu;
        if (lane == 0) pv = wrap;
        int f = 0;
        if (p < n) f = (p == 0) ? 1 : ((v[k] >> 8) != (pv >> 8));
        unsigned bal = __ballot_sync(FULL, f);
        rk[k] = carry + __popc(bal & (0xFFFFFFFFu >> (31 - lane)));
        fl[k] = f;
        carry += __popc(bal);
    }
    return carry;
}

// phase 2: scatter segflag[orig]; leaders also write out_r/out_c (seg-contig,
// streaming); non-leaders append to the duplicate worklist.
template <int R>
__device__ __forceinline__ void row_phase2(int n, int lane, int rowbase, int row,
                                           float* __restrict__ out, int E,
                                           const uint32_t v[4], const uint32_t og[4],
                                           const int rk[4], const int fl[4]) {
    const unsigned FULL = 0xFFFFFFFFu;
    #pragma unroll
    for (int k = 0; k < R; k++) {
        int p = k * 32 + lane;
        uint32_t slot = v[k] & 0xFFu;
        uint32_t o0 = __shfl_sync(FULL, og[0], slot & 31);
        uint32_t o1 = (R > 1) ? __shfl_sync(FULL, og[1], slot & 31) : 0u;
        uint32_t o2 = (R > 2) ? __shfl_sync(FULL, og[2], slot & 31) : 0u;
        uint32_t o3 = (R > 3) ? __shfl_sync(FULL, og[3], slot & 31) : 0u;
        uint32_t r5 = slot >> 5;
        uint32_t orig = (r5 == 0) ? o0 : (r5 == 1) ? o1 : (r5 == 2) ? o2 : o3;
        if (p < n) {
            int seg = rowbase + rk[k] - 1;
            g_segflag[orig] = ((uint32_t)seg << 1) | (uint32_t)fl[k];
            if (fl[k]) {
                out[seg]     = (float)row;
                out[E + seg] = (float)(v[k] >> 8);
            } else {
                int di = atomicAdd(&g_dupcnt, 1);
                g_duplist[di] = ((unsigned long long)(uint32_t)seg << 21)
                              | (unsigned long long)orig;
            }
        }
    }
}

// 2. 16 rows per 512-thread block; warp-per-row; warp-parallel lookback.
__global__ void __launch_bounds__(512)
k_rowsort(float* __restrict__ out, int E) {
    const unsigned FULL = 0xFFFFFFFFu;
    __shared__ int s_bid;
    __shared__ int s_u[ROWS_PER_BLK];
    __shared__ int s_uex[ROWS_PER_BLK];
    __shared__ int s_excl;
    int tid = threadIdx.x, lane = tid & 31, wid = tid >> 5;
    if (tid == 0) s_bid = atomicAdd(&g_blkctr, 1);
    __syncthreads();
    const int bid = s_bid;
    const int row = bid * ROWS_PER_BLK + wid;
    int n = min(g_cnt[row], CAP);
    const unsigned long long* eb = g_bucket + (size_t)row * CAP;

    uint32_t v[4], og[4];
    int rk[4], fl[4];
    int u = 0;
    int mode = (n == 0) ? -1 : (n <= 64) ? 0 : 1;
    if (mode == 0)      u = row_phase1<2>(eb, n, lane, v, og, rk, fl);
    else if (mode == 1) u = row_phase1<4>(eb, n, lane, v, og, rk, fl);

    if (lane == 0) s_u[wid] = u;
    __syncthreads();

    if (wid == 0) {
        int val  = (lane < ROWS_PER_BLK) ? s_u[lane] : 0;
        int incl = val;
        #pragma unroll
        for (int d = 1; d < ROWS_PER_BLK; d <<= 1) {
            int nb = __shfl_up_sync(FULL, incl, d);
            if (lane >= d) incl += nb;
        }
        if (lane < ROWS_PER_BLK) s_uex[lane] = incl - val;
        int agg = __shfl_sync(FULL, incl, ROWS_PER_BLK - 1);

        int excl = 0;
        if (bid == 0) {
            if (lane == 0)
                atomicExch(&g_desc[0], (((unsigned long long)agg) << 2) | 2ull);
        } else {
            if (lane == 0)
                atomicExch(&g_desc[bid], (((unsigned long long)agg) << 2) | 1ull);
            __syncwarp();
            int jtop = bid - 1;
            while (true) {
                int idx = jtop - lane;
                unsigned long long d; unsigned st;
                if (idx >= 0) { d = atomicAdd(&g_desc[idx], 0ull); st = (unsigned)(d & 3ull); }
                else          { d = 2ull; st = 2u; }      // virtual prefix 0
                unsigned pref = __ballot_sync(FULL, st == 2u);
                unsigned nrdy = __ballot_sync(FULL, st == 0u);
                if (pref) {
                    int lp = __ffs(pref) - 1;
                    if ((nrdy & ((lp ? ((1u << lp) - 1u) : 0u))) == 0) {
                        int contrib = (lane <= lp) ? (int)(d >> 2) : 0;
                        #pragma unroll
                        for (int o = 16; o; o >>= 1)
                            contrib += __shfl_down_sync(FULL, contrib, o);
                        excl += __shfl_sync(FULL, contrib, 0);
                        break;
                    }
                } else if (!nrdy) {
                    int contrib = (int)(d >> 2);
                    #pragma unroll
                    for (int o = 16; o; o >>= 1)
                        contrib += __shfl_down_sync(FULL, contrib, o);
                    excl += __shfl_sync(FULL, contrib, 0);
                    jtop -= 32;
                    continue;
                }
                __nanosleep(20);
            }
            if (lane == 0)
                atomicExch(&g_desc[bid],
                           (((unsigned long long)(excl + agg)) << 2) | 2ull);
        }
        if (lane == 0) {
            s_excl = excl;
            if (bid == NBLK_D - 1) g_nu = excl + agg;
        }
    }
    __syncthreads();
    const int rowbase = s_excl + s_uex[wid];

    if (mode == 0)      row_phase2<2>(n, lane, rowbase, row, out, E, v, og, rk, fl);
    else if (mode == 1) row_phase2<4>(n, lane, rowbase, row, out, E, v, og, rk, fl);
}

// 3. fused: arrwp projection pipeline, then raw-edge attr copy, then tail pad.
//    Single WARP per edge: lane owns output cols (2l, 2l+1), W = 64 regs.
//    Halves L1 wavefronts vs the warp-pair layout (8 LDS.128 + 1 STG.64/edge).
static constexpr int SM_FLAG = 16;
static constexpr int SM_ATTR = 4096;              // flags fit below
static constexpr int SM_TOTAL = SM_ATTR + 2 * CHUNK * 128;  // 69632

__global__ void __launch_bounds__(256, 2)
k_fused(const float* __restrict__ eattr, const float* __restrict__ aattr,
        const float* __restrict__ W, float* __restrict__ out,
        int Ee, int Ea) {
    extern __shared__ unsigned char sm[];
    const uint32_t sbase = smem_u32(sm);
    const int E = Ee + Ea;
    float* out_attr = out + 2 * (size_t)E;

    const int tid  = threadIdx.x;
    const int lane = tid & 31;
    const int wrp  = tid >> 5;        // 0..7: each warp owns 32 edges per chunk

    // ---- section A: arrwp projection (double-buffered bulk-async pipeline)
    // per-lane W: rows 2*lane and 2*lane+1, as packed f32x2 over k-pairs
    unsigned long long wa[16], wb[16];
    {
        const unsigned long long* Wa =
            reinterpret_cast<const unsigned long long*>(W + (2 * lane) * 32);
        const unsigned long long* Wb =
            reinterpret_cast<const unsigned long long*>(W + (2 * lane + 1) * 32);
        #pragma unroll
        for (int q = 0; q < 16; q++) { wa[q] = __ldg(Wa + q); wb[q] = __ldg(Wb + q); }
    }

    const int nChunks = (Ea + CHUNK - 1) / CHUNK;
    if (tid == 0) { mbar_init(sbase + 0, 1); mbar_init(sbase + 8, 1); }
    __syncthreads();

    auto issue = [&](int c, int s) {
        int base = c * CHUNK;
        int rem  = min(CHUNK, Ea - base);
        uint32_t attrB = (uint32_t)rem * 128u;
        uint32_t flagB = ((uint32_t)rem * 4u + 15u) & ~15u;
        uint32_t mb = sbase + s * 8;
        mbar_expect_tx(mb, attrB + flagB);
        bulk_copy(sbase + SM_ATTR + s * (CHUNK * 128), aattr + (size_t)base * 32, attrB, mb);
        bulk_copy(sbase + SM_FLAG + s * (CHUNK * 4), &g_segflag[Ee + base], flagB, mb);
    };

    int c0 = blockIdx.x;
    if (c0 < nChunks) {
        if (tid == 0) issue(c0, 0);
        int phase0 = 0, phase1 = 0;
        int li = 0;
        for (int c = c0; c < nChunks; c += gridDim.x, li++) {
            int s = li & 1;
            int cn = c + gridDim.x;
            if (tid == 0 && cn < nChunks) issue(cn, s ^ 1);

            mbar_wait(sbase + s * 8, s ? phase1 : phase0);
            if (s) phase1 ^= 1; else phase0 ^= 1;

            int rem  = min(CHUNK, Ea - c * CHUNK);
            int lbase = wrp * 32;                  // 32 edges per warp
            if (lbase < rem) {
                int cnt = min(32, rem - lbase);
                const uint32_t* flag_s = (const uint32_t*)(sm + SM_FLAG + s * (CHUNK * 4));
                const float* attr_s = (const float*)(sm + SM_ATTR + s * (CHUNK * 128));

                int cnt2 = cnt & ~1;
                for (int t = 0; t < cnt2; t += 2) {
                    uint2 ff = *reinterpret_cast<const uint2*>(flag_s + lbase + t);
                    const ulonglong2* A0 =
                        (const ulonglong2*)(attr_s + (lbase + t) * 32);
                    const ulonglong2* A1 =
                        (const ulonglong2*)(attr_s + (lbase + t + 1) * 32);
                    unsigned long long e0a = 0ull, e0b = 0ull;
                    unsigned long long e1a = 0ull, e1b = 0ull;
                    #pragma unroll
                    for (int q = 0; q < 8; q++) {
                        ulonglong2 p0 = A0[q];           // uniform LDS.128
                        ulonglong2 p1 = A1[q];
                        fma2(e0a, p0.x, wa[2 * q]);
                        fma2(e0a, p0.y, wa[2 * q + 1]);
                        fma2(e0b, p0.x, wb[2 * q]);
                        fma2(e0b, p0.y, wb[2 * q + 1]);
                        fma2(e1a, p1.x, wa[2 * q]);
                        fma2(e1a, p1.y, wa[2 * q + 1]);
                        fma2(e1b, p1.x, wb[2 * q]);
                        fma2(e1b, p1.y, wb[2 * q + 1]);
                    }
                    if (ff.x & 1u) {
                        float2 v; v.x = hsum2(e0a); v.y = hsum2(e0b);
                        reinterpret_cast<float2*>(
                            out_attr + (size_t)(ff.x >> 1) * 64)[lane] = v;
                    }
                    if (ff.y & 1u) {
                        float2 v; v.x = hsum2(e1a); v.y = hsum2(e1b);
                        reinterpret_cast<float2*>(
                            out_attr + (size_t)(ff.y >> 1) * 64)[lane] = v;
                    }
                }
                if (cnt & 1) {
                    int t = cnt2;
                    uint32_t sfe = flag_s[lbase + t];
                    if (sfe & 1u) {
                        const ulonglong2* A0 =
                            (const ulonglong2*)(attr_s + (lbase + t) * 32);
                        unsigned long long e0a = 0ull, e0b = 0ull;
                        #pragma unroll
                        for (int q = 0; q < 8; q++) {
                            ulonglong2 p0 = A0[q];
                            fma2(e0a, p0.x, wa[2 * q]);
                            fma2(e0a, p0.y, wa[2 * q + 1]);
                            fma2(e0b, p0.x, wb[2 * q]);
                            fma2(e0b, p0.y, wb[2 * q + 1]);
                        }
                        float2 v; v.x = hsum2(e0a); v.y = hsum2(e0b);
                        reinterpret_cast<float2*>(
                            out_attr + (size_t)(sfe >> 1) * 64)[lane] = v;
                    }
                }
            }
            __syncthreads();
        }
    }

    // ---- section B: raw-edge attr copy (grid-stride, 2 float4 per thread)
    {
        const int gtid   = blockIdx.x * blockDim.x + tid;
        const int stride = gridDim.x * blockDim.x;
        const float4* eattr4 = reinterpret_cast<const float4*>(eattr);
        float4* out_attr4 = reinterpret_cast<float4*>(out_attr);
        const int total = Ee * 8;                  // 8 x 32B per edge
        for (int i = gtid; i < total; i += stride) {
            int e = i >> 3, h = (i & 7) * 2;
            uint32_t sf = g_segflag[e];
            if (!(sf & 1u)) continue;
            int seg = (int)(sf >> 1);
            float4 v0 = eattr4[(size_t)e * 16 + h];
            float4 v1 = eattr4[(size_t)e * 16 + h + 1];
            out_attr4[(size_t)seg * 16 + h]     = v0;
            out_attr4[(size_t)seg * 16 + h + 1] = v1;
        }
    }

    // ---- section C: tail pad [nu, E)
    {
        const int nu = g_nu;
        const int gtid   = blockIdx.x * blockDim.x + tid;
        const int stride = gridDim.x * blockDim.x;
        for (int i = nu + gtid; i < E; i += stride) {
            out[i]     = -1.0f;
            out[E + i] = -1.0f;
        }
        size_t start = (size_t)nu * 64;
        size_t end   = (size_t)E * 64;
        for (size_t i = start + gtid; i < end; i += (size_t)stride)
            out_attr[i] = 0.0f;
        if (gtid == 0)
            out[2 * (size_t)E + (size_t)E * 64] = (float)nu;
    }
}

// 4. duplicate scatter: worklist-driven (~hundreds of entries); runs AFTER
//    the fused kernel (stream order).
__global__ void k_scatter_dups(const float* __restrict__ eattr,
                               const float* __restrict__ aattr,
                               const float* __restrict__ W,
                               float* __restrict__ out, int Ee, int Ea) {
    int E = Ee + Ea;
    int ndup = g_dupcnt;
    int stride = gridDim.x * blockDim.x;
    for (int i = blockIdx.x * blockDim.x + threadIdx.x; i < ndup; i += stride) {
        unsigned long long ent = g_duplist[i];
        int seg  = (int)(ent >> 21);
        int orig = (int)(ent & 0x1FFFFFull);
        float* orow = out + 2 * (size_t)E + (size_t)seg * 64;
        if (orig < Ee) {
            const float* a = eattr + (size_t)orig * 64;
            for (int j = 0; j < 64; j++) atomicAdd(orow + j, a[j]);
        } else {
            const float* a = aattr + (size_t)(orig - Ee) * 32;
            float av[32];
            #pragma unroll
            for (int k = 0; k < 32; k++) av[k] = a[k];
            for (int j = 0; j < 64; j++) {
                float s = 0.f;
                #pragma unroll
                for (int k = 0; k < 32; k++) s += av[k] * W[j * 32 + k];
                atomicAdd(orow + j, s);
            }
        }
    }
}

// ---------------------------------------------------------------------------
extern "C" void kernel_launch(void* const* d_in, const int* in_sizes, int n_in,
                              void* d_out, int out_size) {
    (void)n_in; (void)out_size;
    const int*   ei    = (const int*)d_in[0];
    const float* eattr = (const float*)d_in[1];
    const int*   ai    = (const int*)d_in[2];
    const float* aattr = (const float*)d_in[3];
    const float* W     = (const float*)d_in[4];
    const int Ee = in_sizes[0] / 2;
    const int Ea = in_sizes[2] / 2;
    const int E  = Ee + Ea;
    float* out = (float*)d_out;

    static bool attr_set = false;
    if (!attr_set) {
        cudaFuncSetAttribute(k_fused,
                             cudaFuncAttributeMaxDynamicSharedMemorySize, SM_TOTAL);
        attr_set = true;
    }

    const int T = 256;
    k_init<<<(NROWS + T - 1) / T, T>>>();
    k_bucket<<<(E + T - 1) / T, T>>>(ei, ai, Ee, Ea);
    k_rowsort<<<NBLK_D, 512>>>(out, E);
    k_fused<<<FUSED_GRID, 256, SM_TOTAL>>>(eattr, aattr, W, out, Ee, Ea);
    k_scatter_dups<<<64, T>>>(eattr, aattr, W, out, Ee, Ea);
}

// round 15
// speedup vs baseline: 1.7451x; 1.0370x over previous
#include <cuda_runtime.h>
#include <cstdint>

static constexpr int MAX_E = 1600000;             // < 2^21 (ids fit 21 bits)
static constexpr int NROWS = 65536;               // row ids < 2^16
static constexpr int CAP   = 128;                 // slots per row bucket
static constexpr int ROWS_PER_BLK = 16;
static constexpr int NBLK_D = NROWS / ROWS_PER_BLK;  // 4096
static constexpr int CHUNK = 256;                 // arrwp rows per pipeline stage
static constexpr int FUSED_GRID = 296;            // 148 SMs x 2 blocks

// Scratch (allocation-free: __device__ globals)
__device__ unsigned long long g_bucket[(size_t)NROWS * CAP];  // (col<<32)|orig
__device__ int g_cnt[NROWS];
__device__ uint32_t g_segflag[MAX_E];             // per ORIGINAL edge: (seg<<1)|leader
__device__ unsigned long long g_desc[NBLK_D];     // lookback: (value<<2)|state
__device__ unsigned long long g_duplist[MAX_E];   // (seg<<21)|orig for duplicates
__device__ int g_dupcnt;
__device__ int g_blkctr;
__device__ int g_nu;

// ---------------------------------------------------------------------------
__device__ __forceinline__ uint32_t smem_u32(const void* p) {
    uint32_t a;
    asm("{ .reg .u64 t; cvta.to.shared.u64 t, %1; cvt.u32.u64 %0, t; }"
        : "=r"(a) : "l"(p));
    return a;
}
__device__ __forceinline__ void fma2(unsigned long long& acc,
                                     unsigned long long a, unsigned long long b) {
    asm("fma.rn.f32x2 %0, %1, %2, %0;" : "+l"(acc) : "l"(a), "l"(b));
}
__device__ __forceinline__ float hsum2(unsigned long long a) {
    float x, y;
    asm("mov.b64 {%0, %1}, %2;" : "=f"(x), "=f"(y) : "l"(a));
    return x + y;
}
__device__ __forceinline__ void mbar_init(uint32_t mbar, uint32_t cnt) {
    asm volatile("mbarrier.init.shared.b64 [%0], %1;" :: "r"(mbar), "r"(cnt) : "memory");
}
__device__ __forceinline__ void mbar_expect_tx(uint32_t mbar, uint32_t bytes) {
    asm volatile("mbarrier.arrive.expect_tx.shared.b64 _, [%0], %1;"
                 :: "r"(mbar), "r"(bytes) : "memory");
}
__device__ __forceinline__ void mbar_wait(uint32_t mbar, uint32_t parity) {
    uint32_t done;
    asm volatile(
        "{ .reg .pred p; mbarrier.try_wait.parity.acquire.cta.shared::cta.b64 p, [%1], %2;"
        " selp.b32 %0, 1, 0, p; }"
        : "=r"(done) : "r"(mbar), "r"(parity) : "memory");
    if (!done) {
        asm volatile(
            "{ .reg .pred P1; WL%=:"
            " mbarrier.try_wait.parity.acquire.cta.shared::cta.b64 P1, [%0], %1, 0x989680;"
            " @P1 bra.uni WD%=; bra.uni WL%=; WD%=: }"
            :: "r"(mbar), "r"(parity) : "memory");
    }
}
__device__ __forceinline__ void bulk_copy(uint32_t dst, const void* src,
                                          uint32_t bytes, uint32_t mbar) {
    asm volatile(
        "cp.async.bulk.shared::cta.global.mbarrier::complete_tx::bytes [%0], [%1], %2, [%3];"
        :: "r"(dst), "l"(src), "r"(bytes), "r"(mbar) : "memory");
}

// ---------------------------------------------------------------------------
// 0. per-launch reset
__global__ void k_init() {
    int i = blockIdx.x * blockDim.x + threadIdx.x;
    if (i < NROWS) g_cnt[i] = 0;
    if (i < NBLK_D) g_desc[i] = 0ull;
    if (i == 0) { g_blkctr = 0; g_dupcnt = 0; }
}

// 1. bucket scatter: g_bucket[row*CAP + slot] = (col<<32)|orig
__global__ void k_bucket(const int* __restrict__ ei, const int* __restrict__ ai,
                         int Ee, int Ea) {
    int E = Ee + Ea;
    int i = blockIdx.x * blockDim.x + threadIdx.x;
    if (i >= E) return;
    int row, col;
    if (i < Ee) { row = ei[i];          col = ei[Ee + i]; }
    else        { int j = i - Ee; row = ai[j]; col = ai[Ea + j]; }
    int slot = atomicAdd(&g_cnt[row], 1);
    if (slot < CAP)
        g_bucket[(size_t)row * CAP + slot] =
            ((unsigned long long)(uint32_t)col << 32) | (unsigned long long)i;
}

// --- per-row machinery: u32 bitonic (size-adapted), flags, ranks ------------
template <int R>
__device__ __forceinline__ int row_phase1(const unsigned long long* __restrict__ eb,
                                          int n, int lane,
                                          uint32_t v[4], uint32_t og[4],
                                          int rk[4], int fl[4]) {
    const unsigned FULL = 0xFFFFFFFFu;
    #pragma unroll
    for (int k = 0; k < R; k++) {
        int p = k * 32 + lane;
        if (p < n) {
            unsigned long long e = eb[p];
            og[k] = (uint32_t)e;
            v[k]  = ((uint32_t)(e >> 32) << 8) | (uint32_t)p;  // (col<<8)|slot
        } else {
            og[k] = 0u;
            v[k]  = 0xFFFFFFFFu;
        }
    }
    #pragma unroll
    for (int s = 2; s <= 32 * R; s <<= 1) {
        #pragma unroll
        for (int d = (32 * R) >> 1; d >= 1; d >>= 1) {
            if (d >= s) continue;
            if (d >= 32) {
                int dd = d >> 5;
                #pragma unroll
                for (int k = 0; k < R; k++) {
                    if ((k & dd) == 0) {
                        int kh = k | dd;
                        bool up = (((k * 32 + lane) & s) == 0);
                        if ((v[k] > v[kh]) == up) { uint32_t t = v[k]; v[k] = v[kh]; v[kh] = t; }
                    }
                }
            } else {
                #pragma unroll
                for (int k = 0; k < R; k++) {
                    int p = k * 32 + lane;
                    bool up = ((p & s) == 0);
                    uint32_t o = __shfl_xor_sync(FULL, v[k], d);
                    bool lower = ((lane & d) == 0);
                    uint32_t mn = v[k] < o ? v[k] : o;
                    uint32_t mx = v[k] < o ? o : v[k];
                    v[k] = (up == lower) ? mn : mx;
                }
            }
        }
    }
    int carry = 0;
    #pragma unroll
    for (int k = 0; k < R; k++) {
        int p = k * 32 + lane;
        uint32_t pv = __shfl_up_sync(FULL, v[k], 1);
        uint32_t wrap = (k > 0) ? __shfl_sync(FULL, v[(k > 0) ? k - 1 : 0], 31)
                                : 0xFFFFFFFFu;
        if (lane == 0) pv = wrap;
        int f = 0;
        if (p < n) f = (p == 0) ? 1 : ((v[k] >> 8) != (pv >> 8));
        unsigned bal = __ballot_sync(FULL, f);
        rk[k] = carry + __popc(bal & (0xFFFFFFFFu >> (31 - lane)));
        fl[k] = f;
        carry += __popc(bal);
    }
    return carry;
}

// phase 2: scatter segflag[orig]; leaders also write out_r/out_c (seg-contig,
// streaming); non-leaders append to the duplicate worklist.
template <int R>
__device__ __forceinline__ void row_phase2(int n, int lane, int rowbase, int row,
                                           float* __restrict__ out, int E,
                                           const uint32_t v[4], const uint32_t og[4],
                                           const int rk[4], const int fl[4]) {
    const unsigned FULL = 0xFFFFFFFFu;
    #pragma unroll
    for (int k = 0; k < R; k++) {
        int p = k * 32 + lane;
        uint32_t slot = v[k] & 0xFFu;
        uint32_t o0 = __shfl_sync(FULL, og[0], slot & 31);
        uint32_t o1 = (R > 1) ? __shfl_sync(FULL, og[1], slot & 31) : 0u;
        uint32_t o2 = (R > 2) ? __shfl_sync(FULL, og[2], slot & 31) : 0u;
        uint32_t o3 = (R > 3) ? __shfl_sync(FULL, og[3], slot & 31) : 0u;
        uint32_t r5 = slot >> 5;
        uint32_t orig = (r5 == 0) ? o0 : (r5 == 1) ? o1 : (r5 == 2) ? o2 : o3;
        if (p < n) {
            int seg = rowbase + rk[k] - 1;
            g_segflag[orig] = ((uint32_t)seg << 1) | (uint32_t)fl[k];
            if (fl[k]) {
                out[seg]     = (float)row;
                out[E + seg] = (float)(v[k] >> 8);
            } else {
                int di = atomicAdd(&g_dupcnt, 1);
                g_duplist[di] = ((unsigned long long)(uint32_t)seg << 21)
                              | (unsigned long long)orig;
            }
        }
    }
}

// 2. 16 rows per 512-thread block; warp-per-row; warp-parallel lookback.
__global__ void __launch_bounds__(512)
k_rowsort(float* __restrict__ out, int E) {
    const unsigned FULL = 0xFFFFFFFFu;
    __shared__ int s_bid;
    __shared__ int s_u[ROWS_PER_BLK];
    __shared__ int s_uex[ROWS_PER_BLK];
    __shared__ int s_excl;
    int tid = threadIdx.x, lane = tid & 31, wid = tid >> 5;
    if (tid == 0) s_bid = atomicAdd(&g_blkctr, 1);
    __syncthreads();
    const int bid = s_bid;
    const int row = bid * ROWS_PER_BLK + wid;
    int n = min(g_cnt[row], CAP);
    const unsigned long long* eb = g_bucket + (size_t)row * CAP;

    uint32_t v[4], og[4];
    int rk[4], fl[4];
    int u = 0;
    int mode = (n == 0) ? -1 : (n <= 64) ? 0 : 1;
    if (mode == 0)      u = row_phase1<2>(eb, n, lane, v, og, rk, fl);
    else if (mode == 1) u = row_phase1<4>(eb, n, lane, v, og, rk, fl);

    if (lane == 0) s_u[wid] = u;
    __syncthreads();

    if (wid == 0) {
        int val  = (lane < ROWS_PER_BLK) ? s_u[lane] : 0;
        int incl = val;
        #pragma unroll
        for (int d = 1; d < ROWS_PER_BLK; d <<= 1) {
            int nb = __shfl_up_sync(FULL, incl, d);
            if (lane >= d) incl += nb;
        }
        if (lane < ROWS_PER_BLK) s_uex[lane] = incl - val;
        int agg = __shfl_sync(FULL, incl, ROWS_PER_BLK - 1);

        int excl = 0;
        if (bid == 0) {
            if (lane == 0)
                atomicExch(&g_desc[0], (((unsigned long long)agg) << 2) | 2ull);
        } else {
            if (lane == 0)
                atomicExch(&g_desc[bid], (((unsigned long long)agg) << 2) | 1ull);
            __syncwarp();
            int jtop = bid - 1;
            while (true) {
                int idx = jtop - lane;
                unsigned long long d; unsigned st;
                if (idx >= 0) { d = atomicAdd(&g_desc[idx], 0ull); st = (unsigned)(d & 3ull); }
                else          { d = 2ull; st = 2u; }      // virtual prefix 0
                unsigned pref = __ballot_sync(FULL, st == 2u);
                unsigned nrdy = __ballot_sync(FULL, st == 0u);
                if (pref) {
                    int lp = __ffs(pref) - 1;
                    if ((nrdy & ((lp ? ((1u << lp) - 1u) : 0u))) == 0) {
                        int contrib = (lane <= lp) ? (int)(d >> 2) : 0;
                        #pragma unroll
                        for (int o = 16; o; o >>= 1)
                            contrib += __shfl_down_sync(FULL, contrib, o);
                        excl += __shfl_sync(FULL, contrib, 0);
                        break;
                    }
                } else if (!nrdy) {
                    int contrib = (int)(d >> 2);
                    #pragma unroll
                    for (int o = 16; o; o >>= 1)
                        contrib += __shfl_down_sync(FULL, contrib, o);
                    excl += __shfl_sync(FULL, contrib, 0);
                    jtop -= 32;
                    continue;
                }
                __nanosleep(20);
            }
            if (lane == 0)
                atomicExch(&g_desc[bid],
                           (((unsigned long long)(excl + agg)) << 2) | 2ull);
        }
        if (lane == 0) {
            s_excl = excl;
            if (bid == NBLK_D - 1) g_nu = excl + agg;
        }
    }
    __syncthreads();
    const int rowbase = s_excl + s_uex[wid];

    if (mode == 0)      row_phase2<2>(n, lane, rowbase, row, out, E, v, og, rk, fl);
    else if (mode == 1) row_phase2<4>(n, lane, rowbase, row, out, E, v, og, rk, fl);
}

// 3. fused: arrwp projection pipeline, then raw-edge attr copy, then tail pad.
//    Single WARP per edge: lane owns output cols (2l, 2l+1), W = 64 regs.
//    Halves L1 wavefronts vs the warp-pair layout (8 LDS.128 + 1 STG.64/edge).
static constexpr int SM_FLAG = 16;
static constexpr int SM_ATTR = 4096;              // flags fit below
static constexpr int SM_TOTAL = SM_ATTR + 2 * CHUNK * 128;  // 69632

__global__ void __launch_bounds__(256, 2)
k_fused(const float* __restrict__ eattr, const float* __restrict__ aattr,
        const float* __restrict__ W, float* __restrict__ out,
        int Ee, int Ea) {
    extern __shared__ unsigned char sm[];
    const uint32_t sbase = smem_u32(sm);
    const int E = Ee + Ea;
    float* out_attr = out + 2 * (size_t)E;

    const int tid  = threadIdx.x;
    const int lane = tid & 31;
    const int wrp  = tid >> 5;        // 0..7: each warp owns 32 edges per chunk

    // ---- section A: arrwp projection (double-buffered bulk-async pipeline)
    // per-lane W: rows 2*lane and 2*lane+1, as packed f32x2 over k-pairs
    unsigned long long wa[16], wb[16];
    {
        const unsigned long long* Wa =
            reinterpret_cast<const unsigned long long*>(W + (2 * lane) * 32);
        const unsigned long long* Wb =
            reinterpret_cast<const unsigned long long*>(W + (2 * lane + 1) * 32);
        #pragma unroll
        for (int q = 0; q < 16; q++) { wa[q] = __ldg(Wa + q); wb[q] = __ldg(Wb + q); }
    }

    const int nChunks = (Ea + CHUNK - 1) / CHUNK;
    if (tid == 0) { mbar_init(sbase + 0, 1); mbar_init(sbase + 8, 1); }
    __syncthreads();

    auto issue = [&](int c, int s) {
        int base = c * CHUNK;
        int rem  = min(CHUNK, Ea - base);
        uint32_t attrB = (uint32_t)rem * 128u;
        uint32_t flagB = ((uint32_t)rem * 4u + 15u) & ~15u;
        uint32_t mb = sbase + s * 8;
        mbar_expect_tx(mb, attrB + flagB);
        bulk_copy(sbase + SM_ATTR + s * (CHUNK * 128), aattr + (size_t)base * 32, attrB, mb);
        bulk_copy(sbase + SM_FLAG + s * (CHUNK * 4), &g_segflag[Ee + base], flagB, mb);
    };

    int c0 = blockIdx.x;
    if (c0 < nChunks) {
        if (tid == 0) issue(c0, 0);
        int phase0 = 0, phase1 = 0;
        int li = 0;
        for (int c = c0; c < nChunks; c += gridDim.x, li++) {
            int s = li & 1;
            int cn = c + gridDim.x;
            if (tid == 0 && cn < nChunks) issue(cn, s ^ 1);

            mbar_wait(sbase + s * 8, s ? phase1 : phase0);
            if (s) phase1 ^= 1; else phase0 ^= 1;

            int rem  = min(CHUNK, Ea - c * CHUNK);
            int lbase = wrp * 32;                  // 32 edges per warp
            if (lbase < rem) {
                int cnt = min(32, rem - lbase);
                const uint32_t* flag_s = (const uint32_t*)(sm + SM_FLAG + s * (CHUNK * 4));
                const float* attr_s = (const float*)(sm + SM_ATTR + s * (CHUNK * 128));

                int cnt2 = cnt & ~1;
                for (int t = 0; t < cnt2; t += 2) {
                    uint2 ff = *reinterpret_cast<const uint2*>(flag_s + lbase + t);
                    const ulonglong2* A0 =
                        (const ulonglong2*)(attr_s + (lbase + t) * 32);
                    const ulonglong2* A1 =
                        (const ulonglong2*)(attr_s + (lbase + t + 1) * 32);
                    unsigned long long e0a = 0ull, e0b = 0ull;
                    unsigned long long e1a = 0ull, e1b = 0ull;
                    #pragma unroll
                    for (int q = 0; q < 8; q++) {
                        ulonglong2 p0 = A0[q];           // uniform LDS.128
                        ulonglong2 p1 = A1[q];
                        fma2(e0a, p0.x, wa[2 * q]);
                        fma2(e0a, p0.y, wa[2 * q + 1]);
                        fma2(e0b, p0.x, wb[2 * q]);
                        fma2(e0b, p0.y, wb[2 * q + 1]);
                        fma2(e1a, p1.x, wa[2 * q]);
                        fma2(e1a, p1.y, wa[2 * q + 1]);
                        fma2(e1b, p1.x, wb[2 * q]);
                        fma2(e1b, p1.y, wb[2 * q + 1]);
                    }
                    if (ff.x & 1u) {
                        float2 v; v.x = hsum2(e0a); v.y = hsum2(e0b);
                        reinterpret_cast<float2*>(
                            out_attr + (size_t)(ff.x >> 1) * 64)[lane] = v;
                    }
                    if (ff.y & 1u) {
                        float2 v; v.x = hsum2(e1a); v.y = hsum2(e1b);
                        reinterpret_cast<float2*>(
                            out_attr + (size_t)(ff.y >> 1) * 64)[lane] = v;
                    }
                }
                if (cnt & 1) {
                    int t = cnt2;
                    uint32_t sfe = flag_s[lbase + t];
                    if (sfe & 1u) {
                        const ulonglong2* A0 =
                            (const ulonglong2*)(attr_s + (lbase + t) * 32);
                        unsigned long long e0a = 0ull, e0b = 0ull;
                        #pragma unroll
                        for (int q = 0; q < 8; q++) {
                            ulonglong2 p0 = A0[q];
                            fma2(e0a, p0.x, wa[2 * q]);
                            fma2(e0a, p0.y, wa[2 * q + 1]);
                            fma2(e0b, p0.x, wb[2 * q]);
                            fma2(e0b, p0.y, wb[2 * q + 1]);
                        }
                        float2 v; v.x = hsum2(e0a); v.y = hsum2(e0b);
                        reinterpret_cast<float2*>(
                            out_attr + (size_t)(sfe >> 1) * 64)[lane] = v;
                    }
                }
            }
            __syncthreads();
        }
    }

    // ---- section B: raw-edge attr copy (grid-stride, 2 float4 per thread)
    {
        const int gtid   = blockIdx.x * blockDim.x + tid;
        const int stride = gridDim.x * blockDim.x;
        const float4* eattr4 = reinterpret_cast<const float4*>(eattr);
        float4* out_attr4 = reinterpret_cast<float4*>(out_attr);
        const int total = Ee * 8;                  // 8 x 32B per edge
        for (int i = gtid; i < total; i += stride) {
            int e = i >> 3, h = (i & 7) * 2;
            uint32_t sf = g_segflag[e];
            if (!(sf & 1u)) continue;
            int seg = (int)(sf >> 1);
            float4 v0 = eattr4[(size_t)e * 16 + h];
            float4 v1 = eattr4[(size_t)e * 16 + h + 1];
            out_attr4[(size_t)seg * 16 + h]     = v0;
            out_attr4[(size_t)seg * 16 + h + 1] = v1;
        }
    }

    // ---- section C: tail pad [nu, E)
    {
        const int nu = g_nu;
        const int gtid   = blockIdx.x * blockDim.x + tid;
        const int stride = gridDim.x * blockDim.x;
        for (int i = nu + gtid; i < E; i += stride) {
            out[i]     = -1.0f;
            out[E + i] = -1.0f;
        }
        size_t start = (size_t)nu * 64;
        size_t end   = (size_t)E * 64;
        for (size_t i = start + gtid; i < end; i += (size_t)stride)
            out_attr[i] = 0.0f;
        if (gtid == 0)
            out[2 * (size_t)E + (size_t)E * 64] = (float)nu;
    }
}

// 4. duplicate scatter: worklist-driven (~hundreds of entries); runs AFTER
//    the fused kernel (stream order).
__global__ void k_scatter_dups(const float* __restrict__ eattr,
                               const float* __restrict__ aattr,
                               const float* __restrict__ W,
                               float* __restrict__ out, int Ee, int Ea) {
    int E = Ee + Ea;
    int ndup = g_dupcnt;
    int stride = gridDim.x * blockDim.x;
    for (int i = blockIdx.x * blockDim.x + threadIdx.x; i < ndup; i += stride) {
        unsigned long long ent = g_duplist[i];
        int seg  = (int)(ent >> 21);
        int orig = (int)(ent & 0x1FFFFFull);
        float* orow = out + 2 * (size_t)E + (size_t)seg * 64;
        if (orig < Ee) {
            const float* a = eattr + (size_t)orig * 64;
            for (int j = 0; j < 64; j++) atomicAdd(orow + j, a[j]);
        } else {
            const float* a = aattr + (size_t)(orig - Ee) * 32;
            float av[32];
            #pragma unroll
            for (int k = 0; k < 32; k++) av[k] = a[k];
            for (int j = 0; j < 64; j++) {
                float s = 0.f;
                #pragma unroll
                for (int k = 0; k < 32; k++) s += av[k] * W[j * 32 + k];
                atomicAdd(orow + j, s);
            }
        }
    }
}

// ---------------------------------------------------------------------------
extern "C" void kernel_launch(void* const* d_in, const int* in_sizes, int n_in,
                              void* d_out, int out_size) {
    (void)n_in; (void)out_size;
    const int*   ei    = (const int*)d_in[0];
    const float* eattr = (const float*)d_in[1];
    const int*   ai    = (const int*)d_in[2];
    const float* aattr = (const float*)d_in[3];
    const float* W     = (const float*)d_in[4];
    const int Ee = in_sizes[0] / 2;
    const int Ea = in_sizes[2] / 2;
    const int E  = Ee + Ea;
    float* out = (float*)d_out;

    static bool attr_set = false;
    if (!attr_set) {
        cudaFuncSetAttribute(k_fused,
                             cudaFuncAttributeMaxDynamicSharedMemorySize, SM_TOTAL);
        attr_set = true;
    }

    const int T = 256;
    k_init<<<(NROWS + T - 1) / T, T>>>();
    k_bucket<<<(E + T - 1) / T, T>>>(ei, ai, Ee, Ea);
    k_rowsort<<<NBLK_D, 512>>>(out, E);
    k_fused<<<FUSED_GRID, 256, SM_TOTAL>>>(eattr, aattr, W, out, Ee, Ea);
    k_scatter_dups<<<64, T>>>(eattr, aattr, W, out, Ee, Ea);
}